// round 1
// baseline (speedup 1.0000x reference)
#include <cuda_runtime.h>

// Problem constants
#define NQ 8
#define R  64
#define Dp 16
#define RLb 16
#define ROb 4

// ---------------------------------------------------------------------------
// Static device scratch (no allocations allowed).
// T intermediates: 16*4*16*64*16*64 = 67,108,864 floats (268 MB) each.
// env: 64*16*4*16*64 = 4,194,304 floats (16 MB) each.
// ---------------------------------------------------------------------------
__device__ float g_bufA[67108864];
__device__ float g_bufB[67108864];
__device__ float g_envA[4194304];
__device__ float g_envB[4194304];
__device__ float g_ud2[NQ * RLb * Dp * Dp * RLb];   // 8 * 65536

// Mixed-radix scatter descriptor: output offset is f(m)+g(n), each a sum of
// (digit * stride) with digits listed innermost-first. Unused digits: radix=1.
struct Scat {
    int radix[4];
    int stride[4];
};

__device__ __forceinline__ int scat_off(int idx, const Scat s) {
    int off = 0;
#pragma unroll
    for (int d = 0; d < 4; d++) {
        off += (idx % s.radix[d]) * s.stride[d];
        idx /= s.radix[d];
    }
    return off;
}

// ---------------------------------------------------------------------------
// Generic TN GEMM with scatter epilogue.
//   A: [K, M]  (k-major, m contiguous)
//   B: [K, N]  (k-major, n contiguous)
//   C[f(m)+g(n)] = sum_k A[k*M+m] * B[k*N+n]
// Block tile 128(M) x 64(N), 128 threads, 8x8 register tile, K chunk = 16.
// Requires: M % 128 == 0, N % 64 == 0, K % 16 == 0 (true for all 5 steps).
// ---------------------------------------------------------------------------
__global__ void __launch_bounds__(128) gemm_tn_scatter(
    const float* __restrict__ A, const float* __restrict__ B,
    float* __restrict__ C, int M, int N, int K, Scat rs, Scat cs)
{
    __shared__ float As[16][128];
    __shared__ float Bs[16][64];

    const int tid = threadIdx.x;
    const int ty = tid >> 3;   // 0..15 : row group (8 rows)
    const int tx = tid & 7;    // 0..7  : col group (8 cols)
    const int m0 = blockIdx.x * 128;
    const int n0 = blockIdx.y * 64;

    float acc[8][8];
#pragma unroll
    for (int r = 0; r < 8; r++)
#pragma unroll
        for (int c = 0; c < 8; c++) acc[r][c] = 0.f;

    // Cooperative load indices (each thread: 16 A elems, 8 B elems per chunk)
    const int ea = tid * 16;
    const int ka = ea >> 7;          // tile row for A load
    const int ma = ea & 127;
    const int eb = tid * 8;
    const int kb = eb >> 6;          // tile row for B load
    const int nb = eb & 63;

    for (int k0 = 0; k0 < K; k0 += 16) {
        const float* Ag = A + (size_t)(k0 + ka) * (size_t)M + (size_t)(m0 + ma);
#pragma unroll
        for (int v = 0; v < 4; v++) {
            float4 t = *(const float4*)(Ag + v * 4);
            *(float4*)&As[ka][ma + v * 4] = t;
        }
        const float* Bg = B + (size_t)(k0 + kb) * (size_t)N + (size_t)(n0 + nb);
#pragma unroll
        for (int v = 0; v < 2; v++) {
            float4 t = *(const float4*)(Bg + v * 4);
            *(float4*)&Bs[kb][nb + v * 4] = t;
        }
        __syncthreads();

#pragma unroll
        for (int kk = 0; kk < 16; kk++) {
            float a[8], b[8];
            *(float4*)&a[0] = *(const float4*)&As[kk][ty * 8];
            *(float4*)&a[4] = *(const float4*)&As[kk][ty * 8 + 4];
            *(float4*)&b[0] = *(const float4*)&Bs[kk][tx * 8];
            *(float4*)&b[4] = *(const float4*)&Bs[kk][tx * 8 + 4];
#pragma unroll
            for (int r = 0; r < 8; r++)
#pragma unroll
                for (int c = 0; c < 8; c++)
                    acc[r][c] += a[r] * b[c];
        }
        __syncthreads();
    }

    // Scatter epilogue
    int fo[8], go[8];
#pragma unroll
    for (int r = 0; r < 8; r++) fo[r] = scat_off(m0 + ty * 8 + r, rs);
#pragma unroll
    for (int c = 0; c < 8; c++) go[c] = scat_off(n0 + tx * 8 + c, cs);
#pragma unroll
    for (int r = 0; r < 8; r++)
#pragma unroll
        for (int c = 0; c < 8; c++)
            C[(size_t)(fo[r] + go[c])] = acc[r][c];
}

// ---------------------------------------------------------------------------
// Ud2[q][(l*16+i)*256 + j*16 + L] = layer[0][q][l][j][i][L]   (real => conj noop)
// ---------------------------------------------------------------------------
__global__ void prep_ud2(const float* __restrict__ layer) {
    int idx = blockIdx.x * blockDim.x + threadIdx.x;
    if (idx >= NQ * RLb * Dp * Dp * RLb) return;
    int Lb = idx & 15; int t = idx >> 4;
    int j  = t & 15;   t >>= 4;
    int i  = t & 15;   t >>= 4;
    int l  = t & 15;   t >>= 4;
    int q  = t;
    g_ud2[idx] = layer[((((size_t)q * 16 + l) * 16 + j) * 16 + i) * 16 + Lb];
}

__global__ void env_init(float* __restrict__ env) {
    int i = blockIdx.x * blockDim.x + threadIdx.x;
    if (i < 4194304) env[i] = (i == 0) ? 1.0f : 0.0f;
}

__global__ void write_out(const float* __restrict__ env, float* __restrict__ out) {
    out[0] = env[0];
}

// ---------------------------------------------------------------------------
extern "C" void kernel_launch(void* const* d_in, const int* in_sizes, int n_in,
                              void* d_out, int out_size) {
    const float* state = (const float*)d_in[0];  // [8, 64, 16, 64]
    const float* layer = (const float*)d_in[1];  // [1, 8, 16, 16, 16, 16]
    const float* oper  = (const float*)d_in[2];  // [8, 4, 16, 16, 4]
    float* out = (float*)d_out;

    float *bufA, *bufB, *envA, *envB, *ud2;
    cudaGetSymbolAddress((void**)&bufA, g_bufA);
    cudaGetSymbolAddress((void**)&bufB, g_bufB);
    cudaGetSymbolAddress((void**)&envA, g_envA);
    cudaGetSymbolAddress((void**)&envB, g_envB);
    cudaGetSymbolAddress((void**)&ud2,  g_ud2);

    prep_ud2<<<512, 1024>>>(layer);
    env_init<<<4096, 1024>>>(envA);

    float* envc = envA;
    float* envn = envB;

    for (int q = 0; q < NQ; q++) {
        const float* S  = state + (size_t)q * 65536;  // [a|b, i|s, A|B]
        const float* U  = layer + (size_t)q * 65536;  // [m, k, s, M]
        const float* O  = oper  + (size_t)q * 4096;   // [o, j, k, O]
        const float* Ud = ud2   + (size_t)q * 65536;  // [(l,i),(j,L)]

        // G1: T1[l,i,o,m,b,A] = sum_a env[a,(l,o,m,b)] * S[a,(i,A)]
        {
            Scat rs = {{64, 16, 4, 16}, {64, 4096, 65536, 4194304}};   // b,m,o,l
            Scat cs = {{64, 16, 1, 1}, {1, 262144, 0, 0}};             // A,i
            gemm_tn_scatter<<<dim3(65536 / 128, 1024 / 64), 128>>>(
                envc, S, bufA, 65536, 1024, 64, rs, cs);
        }
        // G2: T2[o,j,m,b,A,L] = sum_{l,i} T1[(l,i),(o,m,b,A)] * Ud[(l,i),(j,L)]
        {
            Scat rs = {{64, 64, 16, 4}, {16, 1024, 65536, 16777216}};  // A,b,m,o
            Scat cs = {{16, 16, 1, 1}, {1, 1048576, 0, 0}};            // L,j
            gemm_tn_scatter<<<dim3(262144 / 128, 256 / 64), 128>>>(
                bufA, Ud, bufB, 262144, 256, 256, rs, cs);
        }
        // G3: T3[m,k,b,A,L,O] = sum_{o,j} T2[(o,j),(m,b,A,L)] * Oq[(o,j),(k,O)]
        {
            Scat rs = {{16, 64, 64, 16}, {4, 64, 4096, 4194304}};      // L,A,b,m
            Scat cs = {{4, 16, 1, 1}, {1, 262144, 0, 0}};              // O,k
            gemm_tn_scatter<<<dim3(1048576 / 128, 1), 128>>>(
                bufB, O, bufA, 1048576, 64, 64, rs, cs);
        }
        // G4: T4[b,s,A,L,O,M] = sum_{m,k} T3[(m,k),(b,A,L,O)] * Uq[(m,k),(s,M)]
        {
            Scat rs = {{4, 16, 64, 64}, {16, 64, 1024, 1048576}};      // O,L,A,b
            Scat cs = {{16, 16, 1, 1}, {1, 65536, 0, 0}};              // M,s
            gemm_tn_scatter<<<dim3(262144 / 128, 256 / 64), 128>>>(
                bufA, U, bufB, 262144, 256, 256, rs, cs);
        }
        // G5: env'[A,L,O,M,B] = sum_{b,s} T4[(b,s),(A,L,O,M)] * S[(b,s),B]
        {
            Scat rs = {{16, 4, 16, 64}, {64, 1024, 4096, 65536}};      // M,O,L,A
            Scat cs = {{64, 1, 1, 1}, {1, 0, 0, 0}};                   // B
            gemm_tn_scatter<<<dim3(65536 / 128, 1), 128>>>(
                bufB, S, envn, 65536, 64, 1024, rs, cs);
        }

        float* t = envc; envc = envn; envn = t;
    }

    write_out<<<1, 1>>>(envc, out);
}

// round 2
// speedup vs baseline: 1.9493x; 1.9493x over previous
#include <cuda_runtime.h>
#include <cuda_bf16.h>
#include <cstdint>

using bf16 = __nv_bfloat16;

// ---------------------------------------------------------------------------
// Problem constants
// ---------------------------------------------------------------------------
#define NQ 8
#define TSZ 67108864UL   // elements per T plane (one of hi/lo)
#define ESZ 4194304UL    // elements per env plane

// Static device scratch (no allocations allowed).
// Each T buffer: hi plane [0,TSZ), lo plane [TSZ,2*TSZ).  268MB each.
__device__ bf16 g_TA[2 * TSZ];
__device__ bf16 g_TB[2 * TSZ];
__device__ bf16 g_envA[2 * ESZ];
__device__ bf16 g_envB[2 * ESZ];
__device__ bf16 g_S[2 * 524288];   // state split  (native layout)
__device__ bf16 g_U[2 * 524288];   // layer split  (native layout, used as U)
__device__ bf16 g_Ud[2 * 524288];  // permuted U-dagger split
__device__ bf16 g_O[2 * 32768];    // operator split (native layout)

// Mixed-radix scatter descriptor (same convention as round 1).
struct Scat { int radix[4]; int stride[4]; };

__device__ __forceinline__ int scat_off(int idx, const Scat s) {
    int off = 0;
#pragma unroll
    for (int d = 0; d < 4; d++) {
        off += (idx % s.radix[d]) * s.stride[d];
        idx /= s.radix[d];
    }
    return off;
}

// ---------------------------------------------------------------------------
// PTX helpers
// ---------------------------------------------------------------------------
__device__ __forceinline__ uint32_t s2u(const void* p) {
    return (uint32_t)__cvta_generic_to_shared(p);
}
__device__ __forceinline__ void cpa16(uint32_t saddr, const void* g) {
    asm volatile("cp.async.ca.shared.global [%0], [%1], 16;\n" :: "r"(saddr), "l"(g));
}
__device__ __forceinline__ void cp_commit() {
    asm volatile("cp.async.commit_group;\n");
}
__device__ __forceinline__ void cp_wait1() {
    asm volatile("cp.async.wait_group 1;\n");
}
__device__ __forceinline__ void ldsm4t(uint32_t* r, uint32_t addr) {
    asm volatile("ldmatrix.sync.aligned.m8n8.x4.trans.shared.b16 {%0,%1,%2,%3}, [%4];"
                 : "=r"(r[0]), "=r"(r[1]), "=r"(r[2]), "=r"(r[3]) : "r"(addr));
}
__device__ __forceinline__ void mma16816(float* d, const uint32_t* a, const uint32_t* b) {
    asm volatile(
        "mma.sync.aligned.m16n8k16.row.col.f32.bf16.bf16.f32 "
        "{%0,%1,%2,%3},{%4,%5,%6,%7},{%8,%9},{%0,%1,%2,%3};"
        : "+f"(d[0]), "+f"(d[1]), "+f"(d[2]), "+f"(d[3])
        : "r"(a[0]), "r"(a[1]), "r"(a[2]), "r"(a[3]), "r"(b[0]), "r"(b[1]));
}

// ---------------------------------------------------------------------------
// Split-precision bf16 tensor-core GEMM with scatter epilogue.
//   A: [K, M] (m contiguous) bf16, hi plane at A, lo plane at A+Aplane
//   B: [K, N] (n contiguous) bf16, hi/lo likewise
//   acc = Ahi*Bhi + Alo*Bhi + Ahi*Blo  (fp32 accumulate)
//   C[f(m)+g(n)] -> split into hi plane C, lo plane C+Cplane
// BM=128, BK=32, BN template (64/128), 256 threads, 8 warps.
// ---------------------------------------------------------------------------
template <int BN>
__global__ void __launch_bounds__(256, 1) gemm_split(
    const bf16* __restrict__ A, const bf16* __restrict__ B,
    bf16* __restrict__ C, int M, int N, int K,
    size_t Aplane, size_t Bplane, size_t Cplane, Scat rs, Scat cs)
{
    constexpr int BM = 128;
    constexpr int BK = 32;
    constexpr int APITCH = BM + 8;           // 136
    constexpr int BPITCH = BN + 8;
    constexpr int AS_PLANE = BK * APITCH;    // 4352 elems
    constexpr int BS_PLANE = BK * BPITCH;
    constexpr int STAGE = 2 * AS_PLANE + 2 * BS_PLANE;
    constexpr int NT = BN / 16;              // n8-tiles per warp (8 or 4)
    constexpr int MT = 2;                    // m16-tiles per warp

    extern __shared__ bf16 sm[];

    const int tid  = threadIdx.x;
    const int lane = tid & 31;
    const int warp = tid >> 5;
    const int wm = (warp & 3) * 32;
    const int wn = (warp >> 2) * (BN / 2);
    const int m0 = blockIdx.x * BM;
    const int n0 = blockIdx.y * BN;

    float acc[MT][NT][4];
#pragma unroll
    for (int mt = 0; mt < MT; mt++)
#pragma unroll
        for (int nt = 0; nt < NT; nt++)
#pragma unroll
            for (int i = 0; i < 4; i++) acc[mt][nt][i] = 0.f;

    // cooperative load coordinates
    const int lk   = tid >> 3;         // 0..31 : k row
    const int mseg = (tid & 7) * 16;   // 16 elems (2x16B) along m
    const int nseg128 = (tid & 7) * 16;
    const int nseg64  = (tid & 7) * 8;

    auto load_stage = [&](int s, int k0) {
        bf16* base = sm + s * STAGE;
        const bf16* Ag = A + (size_t)(k0 + lk) * (size_t)M + (size_t)(m0 + mseg);
        uint32_t da = s2u(base + lk * APITCH + mseg);
        cpa16(da,      Ag);
        cpa16(da + 16, Ag + 8);
        uint32_t dal = s2u(base + AS_PLANE + lk * APITCH + mseg);
        cpa16(dal,      Ag + Aplane);
        cpa16(dal + 16, Ag + Aplane + 8);
        bf16* bb = base + 2 * AS_PLANE;
        if (BN == 128) {
            const bf16* Bg = B + (size_t)(k0 + lk) * (size_t)N + (size_t)(n0 + nseg128);
            uint32_t db = s2u(bb + lk * BPITCH + nseg128);
            cpa16(db,      Bg);
            cpa16(db + 16, Bg + 8);
            uint32_t dbl = s2u(bb + BS_PLANE + lk * BPITCH + nseg128);
            cpa16(dbl,      Bg + Bplane);
            cpa16(dbl + 16, Bg + Bplane + 8);
        } else {
            const bf16* Bg = B + (size_t)(k0 + lk) * (size_t)N + (size_t)(n0 + nseg64);
            cpa16(s2u(bb + lk * BPITCH + nseg64), Bg);
            cpa16(s2u(bb + BS_PLANE + lk * BPITCH + nseg64), Bg + Bplane);
        }
    };

    const int nchunks = K / BK;
    load_stage(0, 0);
    cp_commit();

    for (int c = 0; c < nchunks; c++) {
        if (c + 1 < nchunks) load_stage((c + 1) & 1, (c + 1) * BK);
        cp_commit();
        cp_wait1();
        __syncthreads();

        const bf16* base = sm + (c & 1) * STAGE;
        const bf16* Ah = base;
        const bf16* Al = base + AS_PLANE;
        const bf16* Bh = base + 2 * AS_PLANE;
        const bf16* Bl = base + 2 * AS_PLANE + BS_PLANE;

#pragma unroll
        for (int kk = 0; kk < BK; kk += 16) {
            // A fragments (m16k16, via trans-ldmatrix from [k][m] smem)
            uint32_t ah[MT][4], al[MT][4];
            const int akr = kk + (lane & 7) + ((lane >> 4) & 1) * 8;
            const int amc = wm + ((lane >> 3) & 1) * 8;
#pragma unroll
            for (int mt = 0; mt < MT; mt++) {
                ldsm4t(ah[mt], s2u(Ah + akr * APITCH + amc + mt * 16));
                ldsm4t(al[mt], s2u(Al + akr * APITCH + amc + mt * 16));
            }
            // B fragments (k16n8 pairs, via trans-ldmatrix from [k][n] smem)
            uint32_t bh[NT / 2][4], bl[NT / 2][4];
            const int bkr = kk + (lane & 7) + ((lane >> 3) & 1) * 8;
            const int bnc = wn + ((lane >> 4) & 1) * 8;
#pragma unroll
            for (int np = 0; np < NT / 2; np++) {
                ldsm4t(bh[np], s2u(Bh + bkr * BPITCH + bnc + np * 16));
                ldsm4t(bl[np], s2u(Bl + bkr * BPITCH + bnc + np * 16));
            }
            // three passes: hi*hi, lo*hi, hi*lo — same accumulators
#pragma unroll
            for (int mt = 0; mt < MT; mt++)
#pragma unroll
                for (int nt = 0; nt < NT; nt++)
                    mma16816(acc[mt][nt], ah[mt], &bh[nt >> 1][(nt & 1) * 2]);
#pragma unroll
            for (int mt = 0; mt < MT; mt++)
#pragma unroll
                for (int nt = 0; nt < NT; nt++)
                    mma16816(acc[mt][nt], al[mt], &bh[nt >> 1][(nt & 1) * 2]);
#pragma unroll
            for (int mt = 0; mt < MT; mt++)
#pragma unroll
                for (int nt = 0; nt < NT; nt++)
                    mma16816(acc[mt][nt], ah[mt], &bl[nt >> 1][(nt & 1) * 2]);
        }
        __syncthreads();
    }

    // Scatter epilogue with hi/lo split
    const int r  = lane >> 2;
    const int c2 = (lane & 3) * 2;
    int fo[MT][2], go[NT][2];
#pragma unroll
    for (int mt = 0; mt < MT; mt++) {
        fo[mt][0] = scat_off(m0 + wm + mt * 16 + r,     rs);
        fo[mt][1] = scat_off(m0 + wm + mt * 16 + r + 8, rs);
    }
#pragma unroll
    for (int nt = 0; nt < NT; nt++) {
        go[nt][0] = scat_off(n0 + wn + nt * 8 + c2,     cs);
        go[nt][1] = scat_off(n0 + wn + nt * 8 + c2 + 1, cs);
    }
#pragma unroll
    for (int mt = 0; mt < MT; mt++)
#pragma unroll
        for (int nt = 0; nt < NT; nt++)
#pragma unroll
            for (int i = 0; i < 4; i++) {
                size_t off = (size_t)(fo[mt][i >> 1] + go[nt][i & 1]);
                float v = acc[mt][nt][i];
                bf16 h = __float2bfloat16(v);
                C[off] = h;
                C[Cplane + off] = __float2bfloat16(v - __bfloat162float(h));
            }
}

// ---------------------------------------------------------------------------
// Prep / utility kernels
// ---------------------------------------------------------------------------
__global__ void split_kernel(const float* __restrict__ src, bf16* __restrict__ dst,
                             size_t plane, int n) {
    int i = blockIdx.x * blockDim.x + threadIdx.x;
    if (i >= n) return;
    float x = src[i];
    bf16 h = __float2bfloat16(x);
    dst[i] = h;
    dst[plane + i] = __float2bfloat16(x - __bfloat162float(h));
}

// Ud[q][(l*16+i)*256 + j*16 + L] = layer[0][q][l][j][i][L]
__global__ void prep_ud_split(const float* __restrict__ layer, bf16* __restrict__ dst,
                              size_t plane) {
    int idx = blockIdx.x * blockDim.x + threadIdx.x;
    if (idx >= 524288) return;
    int Lb = idx & 15; int t = idx >> 4;
    int j  = t & 15;   t >>= 4;
    int i  = t & 15;   t >>= 4;
    int l  = t & 15;   t >>= 4;
    int q  = t;
    float x = layer[((((size_t)q * 16 + l) * 16 + j) * 16 + i) * 16 + Lb];
    bf16 h = __float2bfloat16(x);
    dst[idx] = h;
    dst[plane + idx] = __float2bfloat16(x - __bfloat162float(h));
}

__global__ void env_init(bf16* __restrict__ env) {
    int i = blockIdx.x * blockDim.x + threadIdx.x;
    if (i >= (int)ESZ) return;
    env[i] = __float2bfloat16(i == 0 ? 1.0f : 0.0f);
    env[ESZ + i] = __float2bfloat16(0.0f);
}

__global__ void write_out(const bf16* __restrict__ env, float* __restrict__ out) {
    out[0] = __bfloat162float(env[0]) + __bfloat162float(env[ESZ]);
}

// ---------------------------------------------------------------------------
extern "C" void kernel_launch(void* const* d_in, const int* in_sizes, int n_in,
                              void* d_out, int out_size) {
    const float* state = (const float*)d_in[0];  // [8, 64, 16, 64]
    const float* layer = (const float*)d_in[1];  // [1, 8, 16, 16, 16, 16]
    const float* oper  = (const float*)d_in[2];  // [8, 4, 16, 16, 4]
    float* out = (float*)d_out;

    bf16 *TA, *TB, *envA, *envB, *S, *U, *Ud, *O;
    cudaGetSymbolAddress((void**)&TA,   g_TA);
    cudaGetSymbolAddress((void**)&TB,   g_TB);
    cudaGetSymbolAddress((void**)&envA, g_envA);
    cudaGetSymbolAddress((void**)&envB, g_envB);
    cudaGetSymbolAddress((void**)&S,    g_S);
    cudaGetSymbolAddress((void**)&U,    g_U);
    cudaGetSymbolAddress((void**)&Ud,   g_Ud);
    cudaGetSymbolAddress((void**)&O,    g_O);

    // Opt in to >48KB dynamic smem (idempotent; not a stream op).
    constexpr int SMEM128 = (2 * (2 * 32 * 136 + 2 * 32 * 136)) * 2;  // 69632 B
    constexpr int SMEM64  = (2 * (2 * 32 * 136 + 2 * 32 * 72)) * 2;   // 53248 B
    cudaFuncSetAttribute(gemm_split<128>, cudaFuncAttributeMaxDynamicSharedMemorySize, SMEM128);
    cudaFuncSetAttribute(gemm_split<64>,  cudaFuncAttributeMaxDynamicSharedMemorySize, SMEM64);

    split_kernel<<<2048, 256>>>(state, S, 524288, 524288);
    split_kernel<<<2048, 256>>>(layer, U, 524288, 524288);
    split_kernel<<<128,  256>>>(oper,  O, 32768, 32768);
    prep_ud_split<<<2048, 256>>>(layer, Ud, 524288);
    env_init<<<16384, 256>>>(envA);

    bf16* envc = envA;
    bf16* envn = envB;

    for (int q = 0; q < NQ; q++) {
        const bf16* Sq  = S  + (size_t)q * 65536;
        const bf16* Uq  = U  + (size_t)q * 65536;
        const bf16* Udq = Ud + (size_t)q * 65536;
        const bf16* Oq  = O  + (size_t)q * 4096;

        // G1: T1 = env x S      M=65536 N=1024 K=64   (env -> TA)
        {
            Scat rs = {{64, 16, 4, 16}, {64, 4096, 65536, 4194304}};
            Scat cs = {{64, 16, 1, 1}, {1, 262144, 0, 0}};
            gemm_split<128><<<dim3(65536 / 128, 1024 / 128), 256, SMEM128>>>(
                envc, Sq, TA, 65536, 1024, 64, ESZ, 524288, TSZ, rs, cs);
        }
        // G2: T2 = T1 x Ud      M=262144 N=256 K=256  (TA -> TB)
        {
            Scat rs = {{64, 64, 16, 4}, {16, 1024, 65536, 16777216}};
            Scat cs = {{16, 16, 1, 1}, {1, 1048576, 0, 0}};
            gemm_split<128><<<dim3(262144 / 128, 256 / 128), 256, SMEM128>>>(
                TA, Udq, TB, 262144, 256, 256, TSZ, 524288, TSZ, rs, cs);
        }
        // G3: T3 = T2 x O       M=1048576 N=64 K=64   (TB -> TA)
        {
            Scat rs = {{16, 64, 64, 16}, {4, 64, 4096, 4194304}};
            Scat cs = {{4, 16, 1, 1}, {1, 262144, 0, 0}};
            gemm_split<64><<<dim3(1048576 / 128, 1), 256, SMEM64>>>(
                TB, Oq, TA, 1048576, 64, 64, TSZ, 32768, TSZ, rs, cs);
        }
        // G4: T4 = T3 x U       M=262144 N=256 K=256  (TA -> TB)
        {
            Scat rs = {{4, 16, 64, 64}, {16, 64, 1024, 1048576}};
            Scat cs = {{16, 16, 1, 1}, {1, 65536, 0, 0}};
            gemm_split<128><<<dim3(262144 / 128, 256 / 128), 256, SMEM128>>>(
                TA, Uq, TB, 262144, 256, 256, TSZ, 524288, TSZ, rs, cs);
        }
        // G5: env' = T4 x S     M=65536 N=64 K=1024   (TB -> env)
        {
            Scat rs = {{16, 4, 16, 64}, {64, 1024, 4096, 65536}};
            Scat cs = {{64, 1, 1, 1}, {1, 0, 0, 0}};
            gemm_split<64><<<dim3(65536 / 128, 1), 256, SMEM64>>>(
                TB, Sq, envn, 65536, 64, 1024, TSZ, 524288, ESZ, rs, cs);
        }

        bf16* t = envc; envc = envn; envn = t;
    }

    write_out<<<1, 1>>>(envc, out);
}

// round 4
// speedup vs baseline: 2.9691x; 1.5232x over previous
#include <cuda_runtime.h>
#include <cuda_bf16.h>
#include <cstdint>

using bf16 = __nv_bfloat16;

#define NQ 8
#define TSZ 67108864UL   // elements per T plane
#define ESZ 4194304UL    // elements per env plane

// Static device scratch. hi plane [0,P), lo plane [P,2P).
__device__ bf16 g_TA[2 * TSZ];
__device__ bf16 g_TB[2 * TSZ];
__device__ bf16 g_envA[2 * ESZ];
__device__ bf16 g_envB[2 * ESZ];
__device__ bf16 g_S[2 * 524288];   // state split  (native layout)
__device__ bf16 g_U[2 * 524288];   // layer split  (native layout)
__device__ bf16 g_Ud[2 * 524288];  // permuted U-dagger split
__device__ bf16 g_O[2 * 32768];    // operator split (native layout)

struct Scat { int radix[4]; int stride[4]; };

__device__ __forceinline__ int scat_off(int idx, const Scat s) {
    int off = 0;
#pragma unroll
    for (int d = 0; d < 4; d++) {
        off += (idx % s.radix[d]) * s.stride[d];
        idx /= s.radix[d];
    }
    return off;
}

// ---------------------------------------------------------------------------
// PTX helpers
// ---------------------------------------------------------------------------
__device__ __forceinline__ uint32_t s2u(const void* p) {
    return (uint32_t)__cvta_generic_to_shared(p);
}
__device__ __forceinline__ void cpa16(uint32_t saddr, const void* g) {
    asm volatile("cp.async.ca.shared.global [%0], [%1], 16;\n" :: "r"(saddr), "l"(g));
}
#define CP_COMMIT() asm volatile("cp.async.commit_group;\n")
#define CP_WAIT1()  asm volatile("cp.async.wait_group 1;\n")

__device__ __forceinline__ void ldsm4t(uint32_t* r, uint32_t addr) {
    asm volatile("ldmatrix.sync.aligned.m8n8.x4.trans.shared.b16 {%0,%1,%2,%3}, [%4];"
                 : "=r"(r[0]), "=r"(r[1]), "=r"(r[2]), "=r"(r[3]) : "r"(addr));
}
__device__ __forceinline__ void mma16816(float* d, const uint32_t* a, const uint32_t* b) {
    asm volatile(
        "mma.sync.aligned.m16n8k16.row.col.f32.bf16.bf16.f32 "
        "{%0,%1,%2,%3},{%4,%5,%6,%7},{%8,%9},{%0,%1,%2,%3};"
        : "+f"(d[0]), "+f"(d[1]), "+f"(d[2]), "+f"(d[3])
        : "r"(a[0]), "r"(a[1]), "r"(a[2]), "r"(a[3]), "r"(b[0]), "r"(b[1]));
}

// ---------------------------------------------------------------------------
// Split-precision bf16 mma.sync GEMM, 3-stage cp.async pipeline, 2 CTAs/SM.
//   A: [K, M] (m contiguous) bf16, hi at A, lo at A+Aplane
//   B: [K, N] (n contiguous) bf16, hi/lo likewise
//   acc = Ahi*Bhi + Alo*Bhi + Ahi*Blo  (fp32 accum)
//   C[f(m)+g(n)] split into hi plane C, lo plane C+Cplane
// BM=128, BK=32, BN in {64,128}. 256 threads, 8 warps (4m x 2n).
// ---------------------------------------------------------------------------
template <int BN>
__global__ void __launch_bounds__(256, 2) gemm_split(
    const bf16* __restrict__ A, const bf16* __restrict__ B,
    bf16* __restrict__ C, int M, int N, int K,
    size_t Aplane, size_t Bplane, size_t Cplane, Scat rs, Scat cs)
{
    constexpr int BM = 128;
    constexpr int BK = 32;
    constexpr int APITCH = BM + 8;           // 136
    constexpr int BPITCH = BN + 8;
    constexpr int AS_PLANE = BK * APITCH;
    constexpr int BS_PLANE = BK * BPITCH;
    constexpr int STAGE = 2 * AS_PLANE + 2 * BS_PLANE;
    constexpr int NSTG = 3;
    constexpr int NT = BN / 16;
    constexpr int MT = 2;

    extern __shared__ bf16 sm[];

    const int tid  = threadIdx.x;
    const int lane = tid & 31;
    const int warp = tid >> 5;
    const int wm = (warp & 3) * 32;
    const int wn = (warp >> 2) * (BN / 2);
    const int m0 = blockIdx.x * BM;
    const int n0 = blockIdx.y * BN;

    float acc[MT][NT][4];
#pragma unroll
    for (int mt = 0; mt < MT; mt++)
#pragma unroll
        for (int nt = 0; nt < NT; nt++)
#pragma unroll
            for (int i = 0; i < 4; i++) acc[mt][nt][i] = 0.f;

    const int lk   = tid >> 3;
    const int mseg = (tid & 7) * 16;
    const int nseg128 = (tid & 7) * 16;
    const int nseg64  = (tid & 7) * 8;

    auto load_stage = [&](int s, int k0) {
        bf16* base = sm + s * STAGE;
        const bf16* Ag = A + (size_t)(k0 + lk) * (size_t)M + (size_t)(m0 + mseg);
        uint32_t da = s2u(base + lk * APITCH + mseg);
        cpa16(da,      Ag);
        cpa16(da + 16, Ag + 8);
        uint32_t dal = s2u(base + AS_PLANE + lk * APITCH + mseg);
        cpa16(dal,      Ag + Aplane);
        cpa16(dal + 16, Ag + Aplane + 8);
        bf16* bb = base + 2 * AS_PLANE;
        if (BN == 128) {
            const bf16* Bg = B + (size_t)(k0 + lk) * (size_t)N + (size_t)(n0 + nseg128);
            uint32_t db = s2u(bb + lk * BPITCH + nseg128);
            cpa16(db,      Bg);
            cpa16(db + 16, Bg + 8);
            uint32_t dbl = s2u(bb + BS_PLANE + lk * BPITCH + nseg128);
            cpa16(dbl,      Bg + Bplane);
            cpa16(dbl + 16, Bg + Bplane + 8);
        } else {
            const bf16* Bg = B + (size_t)(k0 + lk) * (size_t)N + (size_t)(n0 + nseg64);
            cpa16(s2u(bb + lk * BPITCH + nseg64), Bg);
            cpa16(s2u(bb + BS_PLANE + lk * BPITCH + nseg64), Bg + Bplane);
        }
    };

    const int nchunks = K / BK;
    load_stage(0, 0);
    CP_COMMIT();
    if (nchunks > 1) load_stage(1, BK);
    CP_COMMIT();

    for (int c = 0; c < nchunks; c++) {
        // groups committed so far = c + 2 ; need group c done -> pending <= 1
        CP_WAIT1();
        __syncthreads();

        // prefetch stage c+2 (overwrites stage used by chunk c-1; all warps
        // finished it before the barrier above)
        if (c + 2 < nchunks) load_stage((c + 2) % NSTG, (c + 2) * BK);
        CP_COMMIT();

        const bf16* base = sm + (c % NSTG) * STAGE;
        const bf16* Ah = base;
        const bf16* Al = base + AS_PLANE;
        const bf16* Bh = base + 2 * AS_PLANE;
        const bf16* Bl = base + 2 * AS_PLANE + BS_PLANE;

#pragma unroll
        for (int kk = 0; kk < BK; kk += 16) {
            uint32_t a0[MT][4], a1[MT][4];
            const int akr = kk + (lane & 7) + ((lane >> 4) & 1) * 8;
            const int amc = wm + ((lane >> 3) & 1) * 8;
#pragma unroll
            for (int mt = 0; mt < MT; mt++) {
                ldsm4t(a0[mt], s2u(Ah + akr * APITCH + amc + mt * 16));
                ldsm4t(a1[mt], s2u(Al + akr * APITCH + amc + mt * 16));
            }
            uint32_t bf[NT / 2][4];
            const int bkr = kk + (lane & 7) + ((lane >> 3) & 1) * 8;
            const int bnc = wn + ((lane >> 4) & 1) * 8;
#pragma unroll
            for (int np = 0; np < NT / 2; np++)
                ldsm4t(bf[np], s2u(Bh + bkr * BPITCH + bnc + np * 16));
            // pass 1: Ahi * Bhi
#pragma unroll
            for (int mt = 0; mt < MT; mt++)
#pragma unroll
                for (int nt = 0; nt < NT; nt++)
                    mma16816(acc[mt][nt], a0[mt], &bf[nt >> 1][(nt & 1) * 2]);
            // pass 2: Alo * Bhi
#pragma unroll
            for (int mt = 0; mt < MT; mt++)
#pragma unroll
                for (int nt = 0; nt < NT; nt++)
                    mma16816(acc[mt][nt], a1[mt], &bf[nt >> 1][(nt & 1) * 2]);
            // reload B-lo into the same registers, pass 3: Ahi * Blo
#pragma unroll
            for (int np = 0; np < NT / 2; np++)
                ldsm4t(bf[np], s2u(Bl + bkr * BPITCH + bnc + np * 16));
#pragma unroll
            for (int mt = 0; mt < MT; mt++)
#pragma unroll
                for (int nt = 0; nt < NT; nt++)
                    mma16816(acc[mt][nt], a0[mt], &bf[nt >> 1][(nt & 1) * 2]);
        }
        __syncthreads();
    }

    // Scatter epilogue with hi/lo split, packed bf16x2 stores.
    const int r  = lane >> 2;
    const int c2 = (lane & 3) * 2;
    int fo[MT][2], go[NT];
#pragma unroll
    for (int mt = 0; mt < MT; mt++) {
        fo[mt][0] = scat_off(m0 + wm + mt * 16 + r,     rs);
        fo[mt][1] = scat_off(m0 + wm + mt * 16 + r + 8, rs);
    }
#pragma unroll
    for (int nt = 0; nt < NT; nt++)
        go[nt] = scat_off(n0 + wn + nt * 8 + c2, cs);   // col c2+1 == +1 (verified)

#pragma unroll
    for (int mt = 0; mt < MT; mt++)
#pragma unroll
        for (int nt = 0; nt < NT; nt++)
#pragma unroll
            for (int h = 0; h < 2; h++) {
                size_t off = (size_t)(fo[mt][h] + go[nt]);
                float v0 = acc[mt][nt][h * 2 + 0];
                float v1 = acc[mt][nt][h * 2 + 1];
                __nv_bfloat162 ph, pl;
                ph.x = __float2bfloat16(v0);
                ph.y = __float2bfloat16(v1);
                pl.x = __float2bfloat16(v0 - __bfloat162float(ph.x));
                pl.y = __float2bfloat16(v1 - __bfloat162float(ph.y));
                *(__nv_bfloat162*)(C + off) = ph;
                *(__nv_bfloat162*)(C + Cplane + off) = pl;
            }
}

// ---------------------------------------------------------------------------
// Prep / utility kernels (identical to round 2)
// ---------------------------------------------------------------------------
__global__ void split_kernel(const float* __restrict__ src, bf16* __restrict__ dst,
                             size_t plane, int n) {
    int i = blockIdx.x * blockDim.x + threadIdx.x;
    if (i >= n) return;
    float x = src[i];
    bf16 h = __float2bfloat16(x);
    dst[i] = h;
    dst[plane + i] = __float2bfloat16(x - __bfloat162float(h));
}

__global__ void prep_ud_split(const float* __restrict__ layer, bf16* __restrict__ dst,
                              size_t plane) {
    int idx = blockIdx.x * blockDim.x + threadIdx.x;
    if (idx >= 524288) return;
    int Lb = idx & 15; int t = idx >> 4;
    int j  = t & 15;   t >>= 4;
    int i  = t & 15;   t >>= 4;
    int l  = t & 15;   t >>= 4;
    int q  = t;
    float x = layer[((((size_t)q * 16 + l) * 16 + j) * 16 + i) * 16 + Lb];
    bf16 h = __float2bfloat16(x);
    dst[idx] = h;
    dst[plane + idx] = __float2bfloat16(x - __bfloat162float(h));
}

__global__ void env_init(bf16* __restrict__ env) {
    int i = blockIdx.x * blockDim.x + threadIdx.x;
    if (i >= (int)ESZ) return;
    env[i] = __float2bfloat16(i == 0 ? 1.0f : 0.0f);
    env[ESZ + i] = __float2bfloat16(0.0f);
}

__global__ void write_out(const bf16* __restrict__ env, float* __restrict__ out) {
    out[0] = __bfloat162float(env[0]) + __bfloat162float(env[ESZ]);
}

// ---------------------------------------------------------------------------
extern "C" void kernel_launch(void* const* d_in, const int* in_sizes, int n_in,
                              void* d_out, int out_size) {
    const float* state = (const float*)d_in[0];  // [8, 64, 16, 64]
    const float* layer = (const float*)d_in[1];  // [1, 8, 16, 16, 16, 16]
    const float* oper  = (const float*)d_in[2];  // [8, 4, 16, 16, 4]
    float* out = (float*)d_out;

    bf16 *TA, *TB, *envA, *envB, *S, *U, *Ud, *O;
    cudaGetSymbolAddress((void**)&TA,   g_TA);
    cudaGetSymbolAddress((void**)&TB,   g_TB);
    cudaGetSymbolAddress((void**)&envA, g_envA);
    cudaGetSymbolAddress((void**)&envB, g_envB);
    cudaGetSymbolAddress((void**)&S,    g_S);
    cudaGetSymbolAddress((void**)&U,    g_U);
    cudaGetSymbolAddress((void**)&Ud,   g_Ud);
    cudaGetSymbolAddress((void**)&O,    g_O);

    // 3-stage pipeline smem: stage = 2*(32*136 + 32*(BN+8)) bf16
    constexpr int SMEM128 = 3 * (2 * (32 * 136) + 2 * (32 * 136)) * 2;  // 104448
    constexpr int SMEM64  = 3 * (2 * (32 * 136) + 2 * (32 * 72)) * 2;   // 79872
    cudaFuncSetAttribute(gemm_split<128>, cudaFuncAttributeMaxDynamicSharedMemorySize, SMEM128);
    cudaFuncSetAttribute(gemm_split<64>,  cudaFuncAttributeMaxDynamicSharedMemorySize, SMEM64);

    split_kernel<<<2048, 256>>>(state, S, 524288, 524288);
    split_kernel<<<2048, 256>>>(layer, U, 524288, 524288);
    split_kernel<<<128,  256>>>(oper,  O, 32768, 32768);
    prep_ud_split<<<2048, 256>>>(layer, Ud, 524288);
    env_init<<<16384, 256>>>(envA);

    bf16* envc = envA;
    bf16* envn = envB;

    for (int q = 0; q < NQ; q++) {
        const bf16* Sq  = S  + (size_t)q * 65536;
        const bf16* Uq  = U  + (size_t)q * 65536;
        const bf16* Udq = Ud + (size_t)q * 65536;
        const bf16* Oq  = O  + (size_t)q * 4096;

        // G1: T1 = env x S      M=65536 N=1024 K=64   (env -> TA)
        {
            Scat rs = {{64, 16, 4, 16}, {64, 4096, 65536, 4194304}};
            Scat cs = {{64, 16, 1, 1}, {1, 262144, 0, 0}};
            gemm_split<128><<<dim3(65536 / 128, 1024 / 128), 256, SMEM128>>>(
                envc, Sq, TA, 65536, 1024, 64, ESZ, 524288, TSZ, rs, cs);
        }
        // G2: T2 = T1 x Ud      M=262144 N=256 K=256  (TA -> TB)
        {
            Scat rs = {{64, 64, 16, 4}, {16, 1024, 65536, 16777216}};
            Scat cs = {{16, 16, 1, 1}, {1, 1048576, 0, 0}};
            gemm_split<128><<<dim3(262144 / 128, 256 / 128), 256, SMEM128>>>(
                TA, Udq, TB, 262144, 256, 256, TSZ, 524288, TSZ, rs, cs);
        }
        // G3: T3 = T2 x O       M=1048576 N=64 K=64   (TB -> TA)
        {
            Scat rs = {{16, 64, 64, 16}, {4, 64, 4096, 4194304}};
            Scat cs = {{4, 16, 1, 1}, {1, 262144, 0, 0}};
            gemm_split<64><<<dim3(1048576 / 128, 1), 256, SMEM64>>>(
                TB, Oq, TA, 1048576, 64, 64, TSZ, 32768, TSZ, rs, cs);
        }
        // G4: T4 = T3 x U       M=262144 N=256 K=256  (TA -> TB)
        {
            Scat rs = {{4, 16, 64, 64}, {16, 64, 1024, 1048576}};
            Scat cs = {{16, 16, 1, 1}, {1, 65536, 0, 0}};
            gemm_split<128><<<dim3(262144 / 128, 256 / 128), 256, SMEM128>>>(
                TA, Uq, TB, 262144, 256, 256, TSZ, 524288, TSZ, rs, cs);
        }
        // G5: env' = T4 x S     M=65536 N=64 K=1024   (TB -> env)
        {
            Scat rs = {{16, 4, 16, 64}, {64, 1024, 4096, 65536}};
            Scat cs = {{64, 1, 1, 1}, {1, 0, 0, 0}};
            gemm_split<64><<<dim3(65536 / 128, 1), 256, SMEM64>>>(
                TB, Sq, envn, 65536, 64, 1024, TSZ, 524288, ESZ, rs, cs);
        }

        bf16* t = envc; envc = envn; envn = t;
    }

    write_out<<<1, 1>>>(envc, out);
}

// round 5
// speedup vs baseline: 3.8783x; 1.3062x over previous
#include <cuda_runtime.h>
#include <cuda_bf16.h>
#include <cstdint>

using bf16 = __nv_bfloat16;

#define NQ 8
#define TSZ 67108864UL   // elements per T plane
#define ESZ 4194304UL    // elements per env plane

// Static device scratch. hi plane [0,P), lo plane [P,2P).
__device__ bf16 g_TA[2 * TSZ];
__device__ bf16 g_TB[2 * TSZ];
__device__ bf16 g_envA[2 * ESZ];
__device__ bf16 g_envB[2 * ESZ];
__device__ bf16 g_S[2 * 524288];   // state split  (native layout)
__device__ bf16 g_U[2 * 524288];   // layer split  (native layout)
__device__ bf16 g_Ud[2 * 524288];  // permuted U-dagger split
__device__ bf16 g_O[2 * 32768];    // operator split (native layout)

struct Scat { int radix[4]; int stride[4]; };

__device__ __forceinline__ int scat_off(int idx, const Scat s) {
    int off = 0;
#pragma unroll
    for (int d = 0; d < 4; d++) {
        off += (idx % s.radix[d]) * s.stride[d];
        idx /= s.radix[d];
    }
    return off;
}

// ---------------------------------------------------------------------------
// PTX helpers
// ---------------------------------------------------------------------------
__device__ __forceinline__ uint32_t s2u(const void* p) {
    return (uint32_t)__cvta_generic_to_shared(p);
}
__device__ __forceinline__ void cpa16(uint32_t saddr, const void* g) {
    asm volatile("cp.async.ca.shared.global [%0], [%1], 16;\n" :: "r"(saddr), "l"(g));
}
#define CP_COMMIT() asm volatile("cp.async.commit_group;\n")
#define CP_WAIT1()  asm volatile("cp.async.wait_group 1;\n")

__device__ __forceinline__ void ldsm4t(uint32_t* r, uint32_t addr) {
    asm volatile("ldmatrix.sync.aligned.m8n8.x4.trans.shared.b16 {%0,%1,%2,%3}, [%4];"
                 : "=r"(r[0]), "=r"(r[1]), "=r"(r[2]), "=r"(r[3]) : "r"(addr));
}
__device__ __forceinline__ void mma16816(float* d, const uint32_t* a, const uint32_t* b) {
    asm volatile(
        "mma.sync.aligned.m16n8k16.row.col.f32.bf16.bf16.f32 "
        "{%0,%1,%2,%3},{%4,%5,%6,%7},{%8,%9},{%0,%1,%2,%3};"
        : "+f"(d[0]), "+f"(d[1]), "+f"(d[2]), "+f"(d[3])
        : "r"(a[0]), "r"(a[1]), "r"(a[2]), "r"(a[3]), "r"(b[0]), "r"(b[1]));
}

// ---------------------------------------------------------------------------
// Split-precision bf16 mma.sync GEMM (identical to round 4).
// ---------------------------------------------------------------------------
template <int BN>
__global__ void __launch_bounds__(256, 2) gemm_split(
    const bf16* __restrict__ A, const bf16* __restrict__ B,
    bf16* __restrict__ C, int M, int N, int K,
    size_t Aplane, size_t Bplane, size_t Cplane, Scat rs, Scat cs)
{
    constexpr int BM = 128;
    constexpr int BK = 32;
    constexpr int APITCH = BM + 8;
    constexpr int BPITCH = BN + 8;
    constexpr int AS_PLANE = BK * APITCH;
    constexpr int BS_PLANE = BK * BPITCH;
    constexpr int STAGE = 2 * AS_PLANE + 2 * BS_PLANE;
    constexpr int NSTG = 3;
    constexpr int NT = BN / 16;
    constexpr int MT = 2;

    extern __shared__ bf16 sm[];

    const int tid  = threadIdx.x;
    const int lane = tid & 31;
    const int warp = tid >> 5;
    const int wm = (warp & 3) * 32;
    const int wn = (warp >> 2) * (BN / 2);
    const int m0 = blockIdx.x * BM;
    const int n0 = blockIdx.y * BN;

    float acc[MT][NT][4];
#pragma unroll
    for (int mt = 0; mt < MT; mt++)
#pragma unroll
        for (int nt = 0; nt < NT; nt++)
#pragma unroll
            for (int i = 0; i < 4; i++) acc[mt][nt][i] = 0.f;

    const int lk   = tid >> 3;
    const int mseg = (tid & 7) * 16;
    const int nseg128 = (tid & 7) * 16;
    const int nseg64  = (tid & 7) * 8;

    auto load_stage = [&](int s, int k0) {
        bf16* base = sm + s * STAGE;
        const bf16* Ag = A + (size_t)(k0 + lk) * (size_t)M + (size_t)(m0 + mseg);
        uint32_t da = s2u(base + lk * APITCH + mseg);
        cpa16(da,      Ag);
        cpa16(da + 16, Ag + 8);
        uint32_t dal = s2u(base + AS_PLANE + lk * APITCH + mseg);
        cpa16(dal,      Ag + Aplane);
        cpa16(dal + 16, Ag + Aplane + 8);
        bf16* bb = base + 2 * AS_PLANE;
        if (BN == 128) {
            const bf16* Bg = B + (size_t)(k0 + lk) * (size_t)N + (size_t)(n0 + nseg128);
            uint32_t db = s2u(bb + lk * BPITCH + nseg128);
            cpa16(db,      Bg);
            cpa16(db + 16, Bg + 8);
            uint32_t dbl = s2u(bb + BS_PLANE + lk * BPITCH + nseg128);
            cpa16(dbl,      Bg + Bplane);
            cpa16(dbl + 16, Bg + Bplane + 8);
        } else {
            const bf16* Bg = B + (size_t)(k0 + lk) * (size_t)N + (size_t)(n0 + nseg64);
            cpa16(s2u(bb + lk * BPITCH + nseg64), Bg);
            cpa16(s2u(bb + BS_PLANE + lk * BPITCH + nseg64), Bg + Bplane);
        }
    };

    const int nchunks = K / BK;
    load_stage(0, 0);
    CP_COMMIT();
    if (nchunks > 1) load_stage(1, BK);
    CP_COMMIT();

    for (int c = 0; c < nchunks; c++) {
        CP_WAIT1();
        __syncthreads();

        if (c + 2 < nchunks) load_stage((c + 2) % NSTG, (c + 2) * BK);
        CP_COMMIT();

        const bf16* base = sm + (c % NSTG) * STAGE;
        const bf16* Ah = base;
        const bf16* Al = base + AS_PLANE;
        const bf16* Bh = base + 2 * AS_PLANE;
        const bf16* Bl = base + 2 * AS_PLANE + BS_PLANE;

#pragma unroll
        for (int kk = 0; kk < BK; kk += 16) {
            uint32_t a0[MT][4], a1[MT][4];
            const int akr = kk + (lane & 7) + ((lane >> 4) & 1) * 8;
            const int amc = wm + ((lane >> 3) & 1) * 8;
#pragma unroll
            for (int mt = 0; mt < MT; mt++) {
                ldsm4t(a0[mt], s2u(Ah + akr * APITCH + amc + mt * 16));
                ldsm4t(a1[mt], s2u(Al + akr * APITCH + amc + mt * 16));
            }
            uint32_t bf[NT / 2][4];
            const int bkr = kk + (lane & 7) + ((lane >> 3) & 1) * 8;
            const int bnc = wn + ((lane >> 4) & 1) * 8;
#pragma unroll
            for (int np = 0; np < NT / 2; np++)
                ldsm4t(bf[np], s2u(Bh + bkr * BPITCH + bnc + np * 16));
#pragma unroll
            for (int mt = 0; mt < MT; mt++)
#pragma unroll
                for (int nt = 0; nt < NT; nt++)
                    mma16816(acc[mt][nt], a0[mt], &bf[nt >> 1][(nt & 1) * 2]);
#pragma unroll
            for (int mt = 0; mt < MT; mt++)
#pragma unroll
                for (int nt = 0; nt < NT; nt++)
                    mma16816(acc[mt][nt], a1[mt], &bf[nt >> 1][(nt & 1) * 2]);
#pragma unroll
            for (int np = 0; np < NT / 2; np++)
                ldsm4t(bf[np], s2u(Bl + bkr * BPITCH + bnc + np * 16));
#pragma unroll
            for (int mt = 0; mt < MT; mt++)
#pragma unroll
                for (int nt = 0; nt < NT; nt++)
                    mma16816(acc[mt][nt], a0[mt], &bf[nt >> 1][(nt & 1) * 2]);
        }
        __syncthreads();
    }

    const int r  = lane >> 2;
    const int c2 = (lane & 3) * 2;
    int fo[MT][2], go[NT];
#pragma unroll
    for (int mt = 0; mt < MT; mt++) {
        fo[mt][0] = scat_off(m0 + wm + mt * 16 + r,     rs);
        fo[mt][1] = scat_off(m0 + wm + mt * 16 + r + 8, rs);
    }
#pragma unroll
    for (int nt = 0; nt < NT; nt++)
        go[nt] = scat_off(n0 + wn + nt * 8 + c2, cs);

#pragma unroll
    for (int mt = 0; mt < MT; mt++)
#pragma unroll
        for (int nt = 0; nt < NT; nt++)
#pragma unroll
            for (int h = 0; h < 2; h++) {
                size_t off = (size_t)(fo[mt][h] + go[nt]);
                float v0 = acc[mt][nt][h * 2 + 0];
                float v1 = acc[mt][nt][h * 2 + 1];
                __nv_bfloat162 ph, pl;
                ph.x = __float2bfloat16(v0);
                ph.y = __float2bfloat16(v1);
                pl.x = __float2bfloat16(v0 - __bfloat162float(ph.x));
                pl.y = __float2bfloat16(v1 - __bfloat162float(ph.y));
                *(__nv_bfloat162*)(C + off) = ph;
                *(__nv_bfloat162*)(C + Cplane + off) = pl;
            }
}

// ---------------------------------------------------------------------------
// Prep kernels (round 2/4)
// ---------------------------------------------------------------------------
__global__ void split_kernel(const float* __restrict__ src, bf16* __restrict__ dst,
                             size_t plane, int n) {
    int i = blockIdx.x * blockDim.x + threadIdx.x;
    if (i >= n) return;
    float x = src[i];
    bf16 h = __float2bfloat16(x);
    dst[i] = h;
    dst[plane + i] = __float2bfloat16(x - __bfloat162float(h));
}

__global__ void prep_ud_split(const float* __restrict__ layer, bf16* __restrict__ dst,
                              size_t plane) {
    int idx = blockIdx.x * blockDim.x + threadIdx.x;
    if (idx >= 524288) return;
    int Lb = idx & 15; int t = idx >> 4;
    int j  = t & 15;   t >>= 4;
    int i  = t & 15;   t >>= 4;
    int l  = t & 15;   t >>= 4;
    int q  = t;
    float x = layer[((((size_t)q * 16 + l) * 16 + j) * 16 + i) * 16 + Lb];
    bf16 h = __float2bfloat16(x);
    dst[idx] = h;
    dst[plane + idx] = __float2bfloat16(x - __bfloat162float(h));
}

// ---------------------------------------------------------------------------
// Site-0 boundary (env0 = delta): exact fp32 chain into env1 pair.
//   C1[A,j,L]   = sum_i S0[0,i,A] * U0[0,j,i,L]
//   C2[A,L,k,O] = sum_j C1[A,j,L] * O0[0,j,k,O]
//   C3[A,L,O,s,M] = sum_k C2[A,L,k,O] * U0[0,k,s,M]
//   env1[A,L,O,M,B] = sum_s C3[A,L,O,s,M] * S0[0,s,B]
// env layout: A*65536 + L*4096 + O*1024 + M*64 + B (hi plane, lo at +ESZ).
// ---------------------------------------------------------------------------
__global__ void s0_c1(const float* __restrict__ st, const float* __restrict__ ly,
                      float* __restrict__ C1) {
    int idx = blockIdx.x * blockDim.x + threadIdx.x;   // 16384
    if (idx >= 16384) return;
    int L = idx & 15, j = (idx >> 4) & 15, A = idx >> 8;
    float s = 0.f;
    for (int i = 0; i < 16; i++)
        s += st[i * 64 + A] * ly[j * 256 + i * 16 + L];
    C1[idx] = s;
}
__global__ void s0_c2(const float* __restrict__ C1, const float* __restrict__ op,
                      float* __restrict__ C2) {
    int idx = blockIdx.x * blockDim.x + threadIdx.x;   // 65536
    if (idx >= 65536) return;
    int O = idx & 3, k = (idx >> 2) & 15, L = (idx >> 6) & 15, A = idx >> 10;
    float s = 0.f;
    for (int j = 0; j < 16; j++)
        s += C1[A * 256 + j * 16 + L] * op[j * 64 + k * 4 + O];
    C2[idx] = s;
}
__global__ void s0_c3(const float* __restrict__ C2, const float* __restrict__ ly,
                      float* __restrict__ C3) {
    int idx = blockIdx.x * blockDim.x + threadIdx.x;   // 1048576
    if (idx >= 1048576) return;
    int M = idx & 15, s5 = (idx >> 4) & 15, O = (idx >> 8) & 3,
        L = (idx >> 10) & 15, A = idx >> 14;
    float s = 0.f;
    for (int k = 0; k < 16; k++)
        s += C2[((A * 16 + L) * 16 + k) * 4 + O] * ly[k * 256 + s5 * 16 + M];
    C3[idx] = s;
}
__global__ void s0_env(const float* __restrict__ C3, const float* __restrict__ st,
                       bf16* __restrict__ env) {
    int idx = blockIdx.x * blockDim.x + threadIdx.x;   // 4194304
    if (idx >= (int)ESZ) return;
    int B = idx & 63, M = (idx >> 6) & 15, O = (idx >> 10) & 3,
        L = (idx >> 12) & 15, A = idx >> 16;
    float v = 0.f;
    for (int s = 0; s < 16; s++)
        v += C3[(((A * 16 + L) * 4 + O) * 16 + s) * 16 + M] * st[s * 64 + B];
    bf16 h = __float2bfloat16(v);
    env[idx] = h;
    env[ESZ + idx] = __float2bfloat16(v - __bfloat162float(h));
}

// ---------------------------------------------------------------------------
// Site-7 boundary (only env8[0] is read): out = sum env7 .* V, V built in fp32.
//   X1[a,l,j]     = sum_i S7[a,i,0] * U7[l,j,i,0]
//   X2[a,l,o,k]   = sum_j X1 * O7[o,j,k,0]
//   X3[a,l,o,m,s] = sum_k X2 * U7[m,k,s,0]
//   out = sum_{a,l,o,m,b,s} env7[a,l,o,m,b] * X3[a,l,o,m,s] * S7[b,s,0]
// ---------------------------------------------------------------------------
__global__ void s7_x1(const float* __restrict__ st, const float* __restrict__ ly,
                      float* __restrict__ X1) {
    int idx = blockIdx.x * blockDim.x + threadIdx.x;   // 16384
    if (idx >= 16384) return;
    int j = idx & 15, l = (idx >> 4) & 15, a = idx >> 8;
    float s = 0.f;
    for (int i = 0; i < 16; i++)
        s += st[a * 1024 + i * 64] * ly[l * 4096 + j * 256 + i * 16];
    X1[idx] = s;
}
__global__ void s7_x2(const float* __restrict__ X1, const float* __restrict__ op,
                      float* __restrict__ X2) {
    int idx = blockIdx.x * blockDim.x + threadIdx.x;   // 65536
    if (idx >= 65536) return;
    int k = idx & 15, o = (idx >> 4) & 3, l = (idx >> 6) & 15, a = idx >> 10;
    float s = 0.f;
    for (int j = 0; j < 16; j++)
        s += X1[(a * 16 + l) * 16 + j] * op[o * 1024 + j * 64 + k * 4];
    X2[idx] = s;
}
__global__ void s7_x3(const float* __restrict__ X2, const float* __restrict__ ly,
                      float* __restrict__ X3) {
    int idx = blockIdx.x * blockDim.x + threadIdx.x;   // 1048576
    if (idx >= 1048576) return;
    int s5 = idx & 15, m = (idx >> 4) & 15, o = (idx >> 8) & 3,
        l = (idx >> 10) & 15, a = idx >> 14;
    float s = 0.f;
    for (int k = 0; k < 16; k++)
        s += X2[((a * 16 + l) * 4 + o) * 16 + k] * ly[m * 4096 + k * 256 + s5 * 16];
    X3[idx] = s;
}
__global__ void s7_dot(const float* __restrict__ X3, const float* __restrict__ st,
                       const bf16* __restrict__ env, float* __restrict__ partial) {
    __shared__ float red[256];
    int t = blockIdx.x * 256 + threadIdx.x;   // t = (a,l,o,m), 65536 total
    float x3[16];
#pragma unroll
    for (int s = 0; s < 16; s++) x3[s] = X3[t * 16 + s];
    size_t base = (size_t)t * 64;             // env offset of (a,l,o,m,b=0)
    float acc = 0.f;
    for (int b = 0; b < 64; b++) {
        float w = 0.f;
#pragma unroll
        for (int s = 0; s < 16; s++) w += x3[s] * st[b * 1024 + s * 64];
        float e = __bfloat162float(env[base + b]) + __bfloat162float(env[ESZ + base + b]);
        acc += e * w;
    }
    red[threadIdx.x] = acc;
    __syncthreads();
    for (int step = 128; step > 0; step >>= 1) {
        if (threadIdx.x < step) red[threadIdx.x] += red[threadIdx.x + step];
        __syncthreads();
    }
    if (threadIdx.x == 0) partial[blockIdx.x] = red[0];
}
__global__ void s7_reduce(const float* __restrict__ partial, float* __restrict__ out) {
    __shared__ float red[256];
    red[threadIdx.x] = partial[threadIdx.x];
    __syncthreads();
    for (int step = 128; step > 0; step >>= 1) {
        if (threadIdx.x < step) red[threadIdx.x] += red[threadIdx.x + step];
        __syncthreads();
    }
    if (threadIdx.x == 0) out[0] = red[0];
}

// ---------------------------------------------------------------------------
extern "C" void kernel_launch(void* const* d_in, const int* in_sizes, int n_in,
                              void* d_out, int out_size) {
    const float* state = (const float*)d_in[0];  // [8, 64, 16, 64]
    const float* layer = (const float*)d_in[1];  // [1, 8, 16, 16, 16, 16]
    const float* oper  = (const float*)d_in[2];  // [8, 4, 16, 16, 4]
    float* out = (float*)d_out;

    bf16 *TA, *TB, *envA, *envB, *S, *U, *Ud, *O;
    cudaGetSymbolAddress((void**)&TA,   g_TA);
    cudaGetSymbolAddress((void**)&TB,   g_TB);
    cudaGetSymbolAddress((void**)&envA, g_envA);
    cudaGetSymbolAddress((void**)&envB, g_envB);
    cudaGetSymbolAddress((void**)&S,    g_S);
    cudaGetSymbolAddress((void**)&U,    g_U);
    cudaGetSymbolAddress((void**)&Ud,   g_Ud);
    cudaGetSymbolAddress((void**)&O,    g_O);

    // fp32 scratch carved out of the (currently unused) T buffers
    float* fA = (float*)TA;   // site-0 scratch (before main loop uses TA)
    float* fB = (float*)TB;   // site-7 scratch (after main loop is done with TB)
    float* C1 = fA,        *C2 = fA + 32768, *C3 = fA + 131072;
    float* X1 = fB,        *X2 = fB + 32768, *X3 = fB + 131072;
    float* partial = fB + 1310720;

    constexpr int SMEM128 = 3 * (2 * (32 * 136) + 2 * (32 * 136)) * 2;  // 104448
    constexpr int SMEM64  = 3 * (2 * (32 * 136) + 2 * (32 * 72)) * 2;   // 79872
    cudaFuncSetAttribute(gemm_split<128>, cudaFuncAttributeMaxDynamicSharedMemorySize, SMEM128);
    cudaFuncSetAttribute(gemm_split<64>,  cudaFuncAttributeMaxDynamicSharedMemorySize, SMEM64);

    split_kernel<<<2048, 256>>>(state, S, 524288, 524288);
    split_kernel<<<2048, 256>>>(layer, U, 524288, 524288);
    split_kernel<<<128,  256>>>(oper,  O, 32768, 32768);
    prep_ud_split<<<2048, 256>>>(layer, Ud, 524288);

    // Site 0 boundary -> env1 into envA (fp32-exact)
    s0_c1<<<64, 256>>>(state, layer, C1);
    s0_c2<<<256, 256>>>(C1, oper, C2);
    s0_c3<<<4096, 256>>>(C2, layer, C3);
    s0_env<<<16384, 256>>>(C3, state, envA);

    bf16* envc = envA;
    bf16* envn = envB;

    for (int q = 1; q <= 6; q++) {
        const bf16* Sq  = S  + (size_t)q * 65536;
        const bf16* Uq  = U  + (size_t)q * 65536;
        const bf16* Udq = Ud + (size_t)q * 65536;
        const bf16* Oq  = O  + (size_t)q * 4096;

        // G1: T1 = env x S      M=65536 N=1024 K=64   (env -> TA)
        {
            Scat rs = {{64, 16, 4, 16}, {64, 4096, 65536, 4194304}};
            Scat cs = {{64, 16, 1, 1}, {1, 262144, 0, 0}};
            gemm_split<128><<<dim3(65536 / 128, 1024 / 128), 256, SMEM128>>>(
                envc, Sq, TA, 65536, 1024, 64, ESZ, 524288, TSZ, rs, cs);
        }
        // G2: T2 = T1 x Ud      M=262144 N=256 K=256  (TA -> TB)
        {
            Scat rs = {{64, 64, 16, 4}, {16, 1024, 65536, 16777216}};
            Scat cs = {{16, 16, 1, 1}, {1, 1048576, 0, 0}};
            gemm_split<128><<<dim3(262144 / 128, 256 / 128), 256, SMEM128>>>(
                TA, Udq, TB, 262144, 256, 256, TSZ, 524288, TSZ, rs, cs);
        }
        // G3: T3 = T2 x O       M=1048576 N=64 K=64   (TB -> TA)
        {
            Scat rs = {{16, 64, 64, 16}, {4, 64, 4096, 4194304}};
            Scat cs = {{4, 16, 1, 1}, {1, 262144, 0, 0}};
            gemm_split<64><<<dim3(1048576 / 128, 1), 256, SMEM64>>>(
                TB, Oq, TA, 1048576, 64, 64, TSZ, 32768, TSZ, rs, cs);
        }
        // G4: T4 = T3 x U       M=262144 N=256 K=256  (TA -> TB)
        {
            Scat rs = {{4, 16, 64, 64}, {16, 64, 1024, 1048576}};
            Scat cs = {{16, 16, 1, 1}, {1, 65536, 0, 0}};
            gemm_split<128><<<dim3(262144 / 128, 256 / 128), 256, SMEM128>>>(
                TA, Uq, TB, 262144, 256, 256, TSZ, 524288, TSZ, rs, cs);
        }
        // G5: env' = T4 x S     M=65536 N=64 K=1024   (TB -> env)
        {
            Scat rs = {{16, 4, 16, 64}, {64, 1024, 4096, 65536}};
            Scat cs = {{64, 1, 1, 1}, {1, 0, 0, 0}};
            gemm_split<64><<<dim3(65536 / 128, 1), 256, SMEM64>>>(
                TB, Sq, envn, 65536, 64, 1024, TSZ, 524288, ESZ, rs, cs);
        }

        bf16* t = envc; envc = envn; envn = t;
    }

    // Site 7 boundary: out = env7 . V (fp32-exact V, deterministic reduce)
    const float* st7 = state + 7 * 65536;
    const float* ly7 = layer + 7 * 65536;
    const float* op7 = oper  + 7 * 4096;
    s7_x1<<<64, 256>>>(st7, ly7, X1);
    s7_x2<<<256, 256>>>(X1, op7, X2);
    s7_x3<<<4096, 256>>>(X2, ly7, X3);
    s7_dot<<<256, 256>>>(X3, st7, envc, partial);
    s7_reduce<<<1, 256>>>(partial, out);
}

// round 6
// speedup vs baseline: 3.9978x; 1.0308x over previous
#include <cuda_runtime.h>
#include <cuda_bf16.h>
#include <cstdint>

using bf16 = __nv_bfloat16;

#define NQ 8
#define TSZ 67108864UL   // elements per T plane
#define ESZ 4194304UL    // elements per env plane

// Static device scratch. hi plane [0,P), lo plane [P,2P).
__device__ bf16 g_TA[2 * TSZ];
__device__ bf16 g_TB[2 * TSZ];
__device__ bf16 g_envA[2 * ESZ];
__device__ bf16 g_envB[2 * ESZ];
__device__ bf16 g_S[2 * 524288];   // state split  (native layout)
__device__ bf16 g_U[2 * 524288];   // layer split  (native layout)
__device__ bf16 g_Ud[2 * 524288];  // permuted U-dagger split
__device__ bf16 g_O[2 * 32768];    // operator split (native layout)

struct Scat { int radix[4]; int stride[4]; };

__device__ __forceinline__ int scat_off(int idx, const Scat s) {
    int off = 0;
#pragma unroll
    for (int d = 0; d < 4; d++) {
        off += (idx % s.radix[d]) * s.stride[d];
        idx /= s.radix[d];
    }
    return off;
}

// ---------------------------------------------------------------------------
// PTX helpers
// ---------------------------------------------------------------------------
__device__ __forceinline__ uint32_t s2u(const void* p) {
    return (uint32_t)__cvta_generic_to_shared(p);
}
__device__ __forceinline__ void cpa16(uint32_t saddr, const void* g) {
    asm volatile("cp.async.ca.shared.global [%0], [%1], 16;\n" :: "r"(saddr), "l"(g));
}
#define CP_COMMIT() asm volatile("cp.async.commit_group;\n")
#define CP_WAIT1()  asm volatile("cp.async.wait_group 1;\n")

__device__ __forceinline__ void ldsm4t(uint32_t* r, uint32_t addr) {
    asm volatile("ldmatrix.sync.aligned.m8n8.x4.trans.shared.b16 {%0,%1,%2,%3}, [%4];"
                 : "=r"(r[0]), "=r"(r[1]), "=r"(r[2]), "=r"(r[3]) : "r"(addr));
}
__device__ __forceinline__ void mma16816(float* d, const uint32_t* a, const uint32_t* b) {
    asm volatile(
        "mma.sync.aligned.m16n8k16.row.col.f32.bf16.bf16.f32 "
        "{%0,%1,%2,%3},{%4,%5,%6,%7},{%8,%9},{%0,%1,%2,%3};"
        : "+f"(d[0]), "+f"(d[1]), "+f"(d[2]), "+f"(d[3])
        : "r"(a[0]), "r"(a[1]), "r"(a[2]), "r"(a[3]), "r"(b[0]), "r"(b[1]));
}

// ---------------------------------------------------------------------------
// Split-precision bf16 mma.sync GEMM (round 4/5 engine, one barrier/chunk).
// ---------------------------------------------------------------------------
template <int BN>
__global__ void __launch_bounds__(256, 2) gemm_split(
    const bf16* __restrict__ A, const bf16* __restrict__ B,
    bf16* __restrict__ C, int M, int N, int K,
    size_t Aplane, size_t Bplane, size_t Cplane, Scat rs, Scat cs)
{
    constexpr int BM = 128;
    constexpr int BK = 32;
    constexpr int APITCH = BM + 8;
    constexpr int BPITCH = BN + 8;
    constexpr int AS_PLANE = BK * APITCH;
    constexpr int BS_PLANE = BK * BPITCH;
    constexpr int STAGE = 2 * AS_PLANE + 2 * BS_PLANE;
    constexpr int NSTG = 3;
    constexpr int NT = BN / 16;
    constexpr int MT = 2;

    extern __shared__ bf16 sm[];

    const int tid  = threadIdx.x;
    const int lane = tid & 31;
    const int warp = tid >> 5;
    const int wm = (warp & 3) * 32;
    const int wn = (warp >> 2) * (BN / 2);
    const int m0 = blockIdx.x * BM;
    const int n0 = blockIdx.y * BN;

    float acc[MT][NT][4];
#pragma unroll
    for (int mt = 0; mt < MT; mt++)
#pragma unroll
        for (int nt = 0; nt < NT; nt++)
#pragma unroll
            for (int i = 0; i < 4; i++) acc[mt][nt][i] = 0.f;

    const int lk   = tid >> 3;
    const int mseg = (tid & 7) * 16;
    const int nseg128 = (tid & 7) * 16;
    const int nseg64  = (tid & 7) * 8;

    auto load_stage = [&](int s, int k0) {
        bf16* base = sm + s * STAGE;
        const bf16* Ag = A + (size_t)(k0 + lk) * (size_t)M + (size_t)(m0 + mseg);
        uint32_t da = s2u(base + lk * APITCH + mseg);
        cpa16(da,      Ag);
        cpa16(da + 16, Ag + 8);
        uint32_t dal = s2u(base + AS_PLANE + lk * APITCH + mseg);
        cpa16(dal,      Ag + Aplane);
        cpa16(dal + 16, Ag + Aplane + 8);
        bf16* bb = base + 2 * AS_PLANE;
        if (BN == 128) {
            const bf16* Bg = B + (size_t)(k0 + lk) * (size_t)N + (size_t)(n0 + nseg128);
            uint32_t db = s2u(bb + lk * BPITCH + nseg128);
            cpa16(db,      Bg);
            cpa16(db + 16, Bg + 8);
            uint32_t dbl = s2u(bb + BS_PLANE + lk * BPITCH + nseg128);
            cpa16(dbl,      Bg + Bplane);
            cpa16(dbl + 16, Bg + Bplane + 8);
        } else {
            const bf16* Bg = B + (size_t)(k0 + lk) * (size_t)N + (size_t)(n0 + nseg64);
            cpa16(s2u(bb + lk * BPITCH + nseg64), Bg);
            cpa16(s2u(bb + BS_PLANE + lk * BPITCH + nseg64), Bg + Bplane);
        }
    };

    const int nchunks = K / BK;
    load_stage(0, 0);
    CP_COMMIT();
    if (nchunks > 1) load_stage(1, BK);
    CP_COMMIT();

    for (int c = 0; c < nchunks; c++) {
        CP_WAIT1();
        __syncthreads();

        // prefetch stage c+2 (its smem held chunk c-1, finished by all warps
        // before the barrier above)
        if (c + 2 < nchunks) load_stage((c + 2) % NSTG, (c + 2) * BK);
        CP_COMMIT();

        const bf16* base = sm + (c % NSTG) * STAGE;
        const bf16* Ah = base;
        const bf16* Al = base + AS_PLANE;
        const bf16* Bh = base + 2 * AS_PLANE;
        const bf16* Bl = base + 2 * AS_PLANE + BS_PLANE;

#pragma unroll
        for (int kk = 0; kk < BK; kk += 16) {
            uint32_t a0[MT][4], a1[MT][4];
            const int akr = kk + (lane & 7) + ((lane >> 4) & 1) * 8;
            const int amc = wm + ((lane >> 3) & 1) * 8;
#pragma unroll
            for (int mt = 0; mt < MT; mt++) {
                ldsm4t(a0[mt], s2u(Ah + akr * APITCH + amc + mt * 16));
                ldsm4t(a1[mt], s2u(Al + akr * APITCH + amc + mt * 16));
            }
            uint32_t bf[NT / 2][4];
            const int bkr = kk + (lane & 7) + ((lane >> 3) & 1) * 8;
            const int bnc = wn + ((lane >> 4) & 1) * 8;
#pragma unroll
            for (int np = 0; np < NT / 2; np++)
                ldsm4t(bf[np], s2u(Bh + bkr * BPITCH + bnc + np * 16));
#pragma unroll
            for (int mt = 0; mt < MT; mt++)
#pragma unroll
                for (int nt = 0; nt < NT; nt++)
                    mma16816(acc[mt][nt], a0[mt], &bf[nt >> 1][(nt & 1) * 2]);
#pragma unroll
            for (int mt = 0; mt < MT; mt++)
#pragma unroll
                for (int nt = 0; nt < NT; nt++)
                    mma16816(acc[mt][nt], a1[mt], &bf[nt >> 1][(nt & 1) * 2]);
#pragma unroll
            for (int np = 0; np < NT / 2; np++)
                ldsm4t(bf[np], s2u(Bl + bkr * BPITCH + bnc + np * 16));
#pragma unroll
            for (int mt = 0; mt < MT; mt++)
#pragma unroll
                for (int nt = 0; nt < NT; nt++)
                    mma16816(acc[mt][nt], a0[mt], &bf[nt >> 1][(nt & 1) * 2]);
        }
        // NOTE: no trailing barrier — next iteration's wait+sync provides the
        // ordering before any smem stage is overwritten.
    }

    const int r  = lane >> 2;
    const int c2 = (lane & 3) * 2;
    int fo[MT][2], go[NT];
#pragma unroll
    for (int mt = 0; mt < MT; mt++) {
        fo[mt][0] = scat_off(m0 + wm + mt * 16 + r,     rs);
        fo[mt][1] = scat_off(m0 + wm + mt * 16 + r + 8, rs);
    }
#pragma unroll
    for (int nt = 0; nt < NT; nt++)
        go[nt] = scat_off(n0 + wn + nt * 8 + c2, cs);

#pragma unroll
    for (int mt = 0; mt < MT; mt++)
#pragma unroll
        for (int nt = 0; nt < NT; nt++)
#pragma unroll
            for (int h = 0; h < 2; h++) {
                size_t off = (size_t)(fo[mt][h] + go[nt]);
                float v0 = acc[mt][nt][h * 2 + 0];
                float v1 = acc[mt][nt][h * 2 + 1];
                __nv_bfloat162 ph, pl;
                ph.x = __float2bfloat16(v0);
                ph.y = __float2bfloat16(v1);
                pl.x = __float2bfloat16(v0 - __bfloat162float(ph.x));
                pl.y = __float2bfloat16(v1 - __bfloat162float(ph.y));
                *(__nv_bfloat162*)(C + off) = ph;
                *(__nv_bfloat162*)(C + Cplane + off) = pl;
            }
}

// ---------------------------------------------------------------------------
// Single fused prep kernel: splits state/layer/oper and gathers+splits Ud.
// Index ranges replicate the proven round-5 kernels exactly.
// ---------------------------------------------------------------------------
__device__ __forceinline__ void put_split_g(bf16* dst, size_t plane, size_t i, float x) {
    bf16 h = __float2bfloat16(x);
    dst[i] = h;
    dst[plane + i] = __float2bfloat16(x - __bfloat162float(h));
}

__global__ void prep_all(const float* __restrict__ state,
                         const float* __restrict__ layer,
                         const float* __restrict__ oper) {
    int idx = blockIdx.x * blockDim.x + threadIdx.x;   // 1,605,632 total
    if (idx < 524288) {
        put_split_g(g_S, 524288, idx, state[idx]);
    } else if (idx < 1048576) {
        int i = idx - 524288;
        put_split_g(g_U, 524288, i, layer[i]);
    } else if (idx < 1081344) {
        int i = idx - 1048576;
        put_split_g(g_O, 32768, i, oper[i]);
    } else {
        int i = idx - 1081344;                          // 524288 Ud entries
        int Lb = i & 15; int t = i >> 4;
        int j  = t & 15;   t >>= 4;
        int ii = t & 15;   t >>= 4;
        int l  = t & 15;   t >>= 4;
        int q  = t;
        float x = layer[((((size_t)q * 16 + l) * 16 + j) * 16 + ii) * 16 + Lb];
        put_split_g(g_Ud, 524288, i, x);
    }
}

// ---------------------------------------------------------------------------
// Fused site-0 boundary (env0 = delta), exact fp32:
//   C1[j,L]       = sum_i S0[0,i,A]·U0[0,j,i,L]                (per-block A)
//   C2[L,k,O]     = sum_j C1[j,L]·O0[0,j,k,O]
//   Y[k,M,B]      = sum_s U0[0,k,s,M]·S0[0,s,B]
//   env1[A,L,O,M,B] = sum_k C2[L,k,O]·Y[k,M,B]
// One block per A (64 blocks, 256 threads). smem: Y 16384f, C2 1024f, C1 256f.
// ---------------------------------------------------------------------------
__global__ void s0_all(const float* __restrict__ st, const float* __restrict__ ly,
                       const float* __restrict__ op, bf16* __restrict__ env) {
    extern __shared__ float sf[];
    float* sY  = sf;           // [k*1024 + M*64 + B]
    float* sC2 = sf + 16384;   // [L*64 + k*4 + O]
    float* sC1 = sf + 17408;   // [j*16 + L]
    const int t = threadIdx.x;
    const int A = blockIdx.x;

    // C1
    {
        int j = t >> 4, L = t & 15;
        float s = 0.f;
        for (int i = 0; i < 16; i++)
            s += st[i * 64 + A] * ly[j * 256 + i * 16 + L];
        sC1[t] = s;
    }
    // Y (independent of C1)
    for (int e = t; e < 16384; e += 256) {
        int k = e >> 10, M = (e >> 6) & 15, B = e & 63;
        float s = 0.f;
        for (int sx = 0; sx < 16; sx++)
            s += ly[k * 256 + sx * 16 + M] * st[sx * 64 + B];
        sY[e] = s;
    }
    __syncthreads();
    // C2
    for (int e = t; e < 1024; e += 256) {
        int L = e >> 6, k = (e >> 2) & 15, O = e & 3;
        float s = 0.f;
        for (int j = 0; j < 16; j++)
            s += sC1[j * 16 + L] * op[j * 64 + k * 4 + O];
        sC2[e] = s;
    }
    __syncthreads();
    // env1 outputs: 65536 per block
    for (int e = t; e < 65536; e += 256) {
        int B = e & 63, M = (e >> 6) & 15, O = (e >> 10) & 3, L = e >> 12;
        float v = 0.f;
#pragma unroll
        for (int k = 0; k < 16; k++)
            v += sC2[L * 64 + k * 4 + O] * sY[k * 1024 + M * 64 + B];
        size_t off = (size_t)A * 65536 + e;
        bf16 h = __float2bfloat16(v);
        env[off] = h;
        env[ESZ + off] = __float2bfloat16(v - __bfloat162float(h));
    }
}

// ---------------------------------------------------------------------------
// Site-7 boundary (round-5, unchanged)
// ---------------------------------------------------------------------------
__global__ void s7_x1(const float* __restrict__ st, const float* __restrict__ ly,
                      float* __restrict__ X1) {
    int idx = blockIdx.x * blockDim.x + threadIdx.x;   // 16384
    if (idx >= 16384) return;
    int j = idx & 15, l = (idx >> 4) & 15, a = idx >> 8;
    float s = 0.f;
    for (int i = 0; i < 16; i++)
        s += st[a * 1024 + i * 64] * ly[l * 4096 + j * 256 + i * 16];
    X1[idx] = s;
}
__global__ void s7_x2(const float* __restrict__ X1, const float* __restrict__ op,
                      float* __restrict__ X2) {
    int idx = blockIdx.x * blockDim.x + threadIdx.x;   // 65536
    if (idx >= 65536) return;
    int k = idx & 15, o = (idx >> 4) & 3, l = (idx >> 6) & 15, a = idx >> 10;
    float s = 0.f;
    for (int j = 0; j < 16; j++)
        s += X1[(a * 16 + l) * 16 + j] * op[o * 1024 + j * 64 + k * 4];
    X2[idx] = s;
}
__global__ void s7_x3(const float* __restrict__ X2, const float* __restrict__ ly,
                      float* __restrict__ X3) {
    int idx = blockIdx.x * blockDim.x + threadIdx.x;   // 1048576
    if (idx >= 1048576) return;
    int s5 = idx & 15, m = (idx >> 4) & 15, o = (idx >> 8) & 3,
        l = (idx >> 10) & 15, a = idx >> 14;
    float s = 0.f;
    for (int k = 0; k < 16; k++)
        s += X2[((a * 16 + l) * 4 + o) * 16 + k] * ly[m * 4096 + k * 256 + s5 * 16];
    X3[idx] = s;
}
__global__ void s7_dot(const float* __restrict__ X3, const float* __restrict__ st,
                       const bf16* __restrict__ env, float* __restrict__ partial) {
    __shared__ float red[256];
    int t = blockIdx.x * 256 + threadIdx.x;   // (a,l,o,m), 65536 total
    float x3[16];
#pragma unroll
    for (int s = 0; s < 16; s++) x3[s] = X3[t * 16 + s];
    size_t base = (size_t)t * 64;
    float acc = 0.f;
    for (int b = 0; b < 64; b++) {
        float w = 0.f;
#pragma unroll
        for (int s = 0; s < 16; s++) w += x3[s] * st[b * 1024 + s * 64];
        float e = __bfloat162float(env[base + b]) + __bfloat162float(env[ESZ + base + b]);
        acc += e * w;
    }
    red[threadIdx.x] = acc;
    __syncthreads();
    for (int step = 128; step > 0; step >>= 1) {
        if (threadIdx.x < step) red[threadIdx.x] += red[threadIdx.x + step];
        __syncthreads();
    }
    if (threadIdx.x == 0) partial[blockIdx.x] = red[0];
}
__global__ void s7_reduce(const float* __restrict__ partial, float* __restrict__ out) {
    __shared__ float red[256];
    red[threadIdx.x] = partial[threadIdx.x];
    __syncthreads();
    for (int step = 128; step > 0; step >>= 1) {
        if (threadIdx.x < step) red[threadIdx.x] += red[threadIdx.x + step];
        __syncthreads();
    }
    if (threadIdx.x == 0) out[0] = red[0];
}

// ---------------------------------------------------------------------------
extern "C" void kernel_launch(void* const* d_in, const int* in_sizes, int n_in,
                              void* d_out, int out_size) {
    const float* state = (const float*)d_in[0];  // [8, 64, 16, 64]
    const float* layer = (const float*)d_in[1];  // [1, 8, 16, 16, 16, 16]
    const float* oper  = (const float*)d_in[2];  // [8, 4, 16, 16, 4]
    float* out = (float*)d_out;

    bf16 *TA, *TB, *envA, *envB, *S, *U, *Ud, *O;
    cudaGetSymbolAddress((void**)&TA,   g_TA);
    cudaGetSymbolAddress((void**)&TB,   g_TB);
    cudaGetSymbolAddress((void**)&envA, g_envA);
    cudaGetSymbolAddress((void**)&envB, g_envB);
    cudaGetSymbolAddress((void**)&S,    g_S);
    cudaGetSymbolAddress((void**)&U,    g_U);
    cudaGetSymbolAddress((void**)&Ud,   g_Ud);
    cudaGetSymbolAddress((void**)&O,    g_O);

    // fp32 scratch carved from TB (used only after main loop frees it)
    float* fB = (float*)TB;
    float* X1 = fB, *X2 = fB + 32768, *X3 = fB + 131072;
    float* partial = fB + 1310720;

    constexpr int SMEM128 = 3 * (2 * (32 * 136) + 2 * (32 * 136)) * 2;  // 104448
    constexpr int SMEM64  = 3 * (2 * (32 * 136) + 2 * (32 * 72)) * 2;   // 79872
    constexpr int SMEM_S0 = 17664 * 4;                                  // 70656
    cudaFuncSetAttribute(gemm_split<128>, cudaFuncAttributeMaxDynamicSharedMemorySize, SMEM128);
    cudaFuncSetAttribute(gemm_split<64>,  cudaFuncAttributeMaxDynamicSharedMemorySize, SMEM64);
    cudaFuncSetAttribute(s0_all,          cudaFuncAttributeMaxDynamicSharedMemorySize, SMEM_S0);

    // [0] fused prep, [1] fused site-0 boundary -> env1 in envA
    prep_all<<<6272, 256>>>(state, layer, oper);
    s0_all<<<64, 256, SMEM_S0>>>(state, layer, oper, envA);

    bf16* envc = envA;
    bf16* envn = envB;

    for (int q = 1; q <= 6; q++) {
        const bf16* Sq  = S  + (size_t)q * 65536;
        const bf16* Uq  = U  + (size_t)q * 65536;
        const bf16* Udq = Ud + (size_t)q * 65536;
        const bf16* Oq  = O  + (size_t)q * 4096;

        // G1: T1 = env x S      M=65536 N=1024 K=64   (env -> TA)
        {
            Scat rs = {{64, 16, 4, 16}, {64, 4096, 65536, 4194304}};
            Scat cs = {{64, 16, 1, 1}, {1, 262144, 0, 0}};
            gemm_split<128><<<dim3(65536 / 128, 1024 / 128), 256, SMEM128>>>(
                envc, Sq, TA, 65536, 1024, 64, ESZ, 524288, TSZ, rs, cs);
        }
        // G2: T2 = T1 x Ud      M=262144 N=256 K=256  (TA -> TB)
        {
            Scat rs = {{64, 64, 16, 4}, {16, 1024, 65536, 16777216}};
            Scat cs = {{16, 16, 1, 1}, {1, 1048576, 0, 0}};
            gemm_split<128><<<dim3(262144 / 128, 256 / 128), 256, SMEM128>>>(
                TA, Udq, TB, 262144, 256, 256, TSZ, 524288, TSZ, rs, cs);
        }
        // G3: T3 = T2 x O       M=1048576 N=64 K=64   (TB -> TA)
        {
            Scat rs = {{16, 64, 64, 16}, {4, 64, 4096, 4194304}};
            Scat cs = {{4, 16, 1, 1}, {1, 262144, 0, 0}};
            gemm_split<64><<<dim3(1048576 / 128, 1), 256, SMEM64>>>(
                TB, Oq, TA, 1048576, 64, 64, TSZ, 32768, TSZ, rs, cs);
        }
        // G4: T4 = T3 x U       M=262144 N=256 K=256  (TA -> TB)
        {
            Scat rs = {{4, 16, 64, 64}, {16, 64, 1024, 1048576}};
            Scat cs = {{16, 16, 1, 1}, {1, 65536, 0, 0}};
            gemm_split<128><<<dim3(262144 / 128, 256 / 128), 256, SMEM128>>>(
                TA, Uq, TB, 262144, 256, 256, TSZ, 524288, TSZ, rs, cs);
        }
        // G5: env' = T4 x S     M=65536 N=64 K=1024   (TB -> env)
        {
            Scat rs = {{16, 4, 16, 64}, {64, 1024, 4096, 65536}};
            Scat cs = {{64, 1, 1, 1}, {1, 0, 0, 0}};
            gemm_split<64><<<dim3(65536 / 128, 1), 256, SMEM64>>>(
                TB, Sq, envn, 65536, 64, 1024, TSZ, 524288, ESZ, rs, cs);
        }

        bf16* t = envc; envc = envn; envn = t;
    }

    // Site 7 boundary: out = env7 . V (fp32-exact V, deterministic reduce)
    const float* st7 = state + 7 * 65536;
    const float* ly7 = layer + 7 * 65536;
    const float* op7 = oper  + 7 * 4096;
    s7_x1<<<64, 256>>>(st7, ly7, X1);
    s7_x2<<<256, 256>>>(X1, op7, X2);
    s7_x3<<<4096, 256>>>(X2, ly7, X3);
    s7_dot<<<256, 256>>>(X3, st7, envc, partial);
    s7_reduce<<<1, 256>>>(partial, out);
}

// round 9
// speedup vs baseline: 4.3564x; 1.0897x over previous
#include <cuda_runtime.h>
#include <cuda_bf16.h>
#include <cstdint>

using bf16 = __nv_bfloat16;

#define NQ 8
#define TSZ 67108864UL   // elements per T plane
#define ESZ 4194304UL    // elements per env plane

// Static device scratch. hi plane [0,P), lo plane [P,2P).
__device__ bf16 g_TA[2 * TSZ];
__device__ bf16 g_TB[2 * TSZ];
__device__ bf16 g_envA[2 * ESZ];
__device__ bf16 g_envB[2 * ESZ];
__device__ bf16 g_S[2 * 524288];   // state split  (native layout)
__device__ bf16 g_U[2 * 524288];   // layer split  (native layout)
__device__ bf16 g_Ud[2 * 524288];  // permuted U-dagger split
__device__ bf16 g_O[2 * 32768];    // operator split (native layout)

struct Scat { int radix[4]; int stride[4]; };

__device__ __forceinline__ int scat_off(int idx, const Scat s) {
    int off = 0;
#pragma unroll
    for (int d = 0; d < 4; d++) {
        off += (idx % s.radix[d]) * s.stride[d];
        idx /= s.radix[d];
    }
    return off;
}

// ---------------------------------------------------------------------------
// PTX helpers
// ---------------------------------------------------------------------------
__device__ __forceinline__ uint32_t s2u(const void* p) {
    return (uint32_t)__cvta_generic_to_shared(p);
}
__device__ __forceinline__ void cpa16(uint32_t saddr, const void* g) {
    asm volatile("cp.async.cg.shared.global [%0], [%1], 16;\n" :: "r"(saddr), "l"(g));
}
#define CP_COMMIT() asm volatile("cp.async.commit_group;\n")
#define CP_WAIT1()  asm volatile("cp.async.wait_group 1;\n")

__device__ __forceinline__ void ldsm4t(uint32_t* r, uint32_t addr) {
    asm volatile("ldmatrix.sync.aligned.m8n8.x4.trans.shared.b16 {%0,%1,%2,%3}, [%4];"
                 : "=r"(r[0]), "=r"(r[1]), "=r"(r[2]), "=r"(r[3]) : "r"(addr));
}
__device__ __forceinline__ void mma16816(float* d, const uint32_t* a, const uint32_t* b) {
    asm volatile(
        "mma.sync.aligned.m16n8k16.row.col.f32.bf16.bf16.f32 "
        "{%0,%1,%2,%3},{%4,%5,%6,%7},{%8,%9},{%0,%1,%2,%3};"
        : "+f"(d[0]), "+f"(d[1]), "+f"(d[2]), "+f"(d[3])
        : "r"(a[0]), "r"(a[1]), "r"(a[2]), "r"(a[3]), "r"(b[0]), "r"(b[1]));
}

__device__ __forceinline__ void store_pair(bf16* C, size_t Cplane, size_t off,
                                           float v0, float v1) {
    __nv_bfloat162 ph, pl;
    ph.x = __float2bfloat16(v0);
    ph.y = __float2bfloat16(v1);
    pl.x = __float2bfloat16(v0 - __bfloat162float(ph.x));
    pl.y = __float2bfloat16(v1 - __bfloat162float(ph.y));
    *(__nv_bfloat162*)(C + off) = ph;
    *(__nv_bfloat162*)(C + Cplane + off) = pl;
}

// ---------------------------------------------------------------------------
// Split-precision bf16 3-pass GEMM, BM=128, BN=128 (round-6 engine, .cg).
//   A: [K, M] (m contig) bf16 pair; B: [K, N] (n contig) bf16 pair.
//   acc = Ahi*Bhi + Alo*Bhi + Ahi*Blo  (fp32 accum)
// ---------------------------------------------------------------------------
__global__ void __launch_bounds__(256, 2) gemm_big(
    const bf16* __restrict__ A, const bf16* __restrict__ B,
    bf16* __restrict__ C, int M, int N, int K,
    size_t Aplane, size_t Bplane, size_t Cplane, Scat rs, Scat cs)
{
    constexpr int BM = 128, BN = 128, BK = 32;
    constexpr int APITCH = BM + 8;
    constexpr int BPITCH = BN + 8;
    constexpr int AS_PLANE = BK * APITCH;
    constexpr int BS_PLANE = BK * BPITCH;
    constexpr int STAGE = 2 * AS_PLANE + 2 * BS_PLANE;
    constexpr int NSTG = 3;
    constexpr int NT = BN / 16;   // 8
    constexpr int MT = 2;

    extern __shared__ bf16 sm[];

    const int tid  = threadIdx.x;
    const int lane = tid & 31;
    const int warp = tid >> 5;
    const int wm = (warp & 3) * 32;
    const int wn = (warp >> 2) * (BN / 2);
    const int m0 = blockIdx.x * BM;
    const int n0 = blockIdx.y * BN;

    float acc[MT][NT][4];
#pragma unroll
    for (int mt = 0; mt < MT; mt++)
#pragma unroll
        for (int nt = 0; nt < NT; nt++)
#pragma unroll
            for (int i = 0; i < 4; i++) acc[mt][nt][i] = 0.f;

    const int lk   = tid >> 3;
    const int mseg = (tid & 7) * 16;

    auto load_stage = [&](int s, int k0) {
        bf16* base = sm + s * STAGE;
        const bf16* Ag = A + (size_t)(k0 + lk) * (size_t)M + (size_t)(m0 + mseg);
        uint32_t da = s2u(base + lk * APITCH + mseg);
        cpa16(da,      Ag);
        cpa16(da + 16, Ag + 8);
        uint32_t dal = s2u(base + AS_PLANE + lk * APITCH + mseg);
        cpa16(dal,      Ag + Aplane);
        cpa16(dal + 16, Ag + Aplane + 8);
        bf16* bb = base + 2 * AS_PLANE;
        const bf16* Bg = B + (size_t)(k0 + lk) * (size_t)N + (size_t)(n0 + mseg);
        uint32_t db = s2u(bb + lk * BPITCH + mseg);
        cpa16(db,      Bg);
        cpa16(db + 16, Bg + 8);
        uint32_t dbl = s2u(bb + BS_PLANE + lk * BPITCH + mseg);
        cpa16(dbl,      Bg + Bplane);
        cpa16(dbl + 16, Bg + Bplane + 8);
    };

    const int nchunks = K / BK;
    load_stage(0, 0);
    CP_COMMIT();
    if (nchunks > 1) load_stage(1, BK);
    CP_COMMIT();

    for (int c = 0; c < nchunks; c++) {
        CP_WAIT1();
        __syncthreads();

        if (c + 2 < nchunks) load_stage((c + 2) % NSTG, (c + 2) * BK);
        CP_COMMIT();

        const bf16* base = sm + (c % NSTG) * STAGE;
        const bf16* Ah = base;
        const bf16* Al = base + AS_PLANE;
        const bf16* Bh = base + 2 * AS_PLANE;
        const bf16* Bl = base + 2 * AS_PLANE + BS_PLANE;

#pragma unroll
        for (int kk = 0; kk < BK; kk += 16) {
            uint32_t a0[MT][4], a1[MT][4];
            const int akr = kk + (lane & 7) + ((lane >> 4) & 1) * 8;
            const int amc = wm + ((lane >> 3) & 1) * 8;
#pragma unroll
            for (int mt = 0; mt < MT; mt++) {
                ldsm4t(a0[mt], s2u(Ah + akr * APITCH + amc + mt * 16));
                ldsm4t(a1[mt], s2u(Al + akr * APITCH + amc + mt * 16));
            }
            uint32_t bf[NT / 2][4];
            const int bkr = kk + (lane & 7) + ((lane >> 3) & 1) * 8;
            const int bnc = wn + ((lane >> 4) & 1) * 8;
#pragma unroll
            for (int np = 0; np < NT / 2; np++)
                ldsm4t(bf[np], s2u(Bh + bkr * BPITCH + bnc + np * 16));
#pragma unroll
            for (int mt = 0; mt < MT; mt++)
#pragma unroll
                for (int nt = 0; nt < NT; nt++)
                    mma16816(acc[mt][nt], a0[mt], &bf[nt >> 1][(nt & 1) * 2]);
#pragma unroll
            for (int mt = 0; mt < MT; mt++)
#pragma unroll
                for (int nt = 0; nt < NT; nt++)
                    mma16816(acc[mt][nt], a1[mt], &bf[nt >> 1][(nt & 1) * 2]);
#pragma unroll
            for (int np = 0; np < NT / 2; np++)
                ldsm4t(bf[np], s2u(Bl + bkr * BPITCH + bnc + np * 16));
#pragma unroll
            for (int mt = 0; mt < MT; mt++)
#pragma unroll
                for (int nt = 0; nt < NT; nt++)
                    mma16816(acc[mt][nt], a0[mt], &bf[nt >> 1][(nt & 1) * 2]);
        }
    }

    const int r  = lane >> 2;
    const int c2 = (lane & 3) * 2;
    int fo[MT][2], go[NT];
#pragma unroll
    for (int mt = 0; mt < MT; mt++) {
        fo[mt][0] = scat_off(m0 + wm + mt * 16 + r,     rs);
        fo[mt][1] = scat_off(m0 + wm + mt * 16 + r + 8, rs);
    }
#pragma unroll
    for (int nt = 0; nt < NT; nt++)
        go[nt] = scat_off(n0 + wn + nt * 8 + c2, cs);

#pragma unroll
    for (int mt = 0; mt < MT; mt++)
#pragma unroll
        for (int nt = 0; nt < NT; nt++)
#pragma unroll
            for (int h = 0; h < 2; h++)
                store_pair(C, Cplane, (size_t)(fo[mt][h] + go[nt]),
                           acc[mt][nt][h * 2], acc[mt][nt][h * 2 + 1]);
}

// ---------------------------------------------------------------------------
// High-occupancy small-tile variant: BM=64, BN=64, 3 CTAs/SM.
// Warp layout: 4 m-groups x 2 n-groups; warp tile 16m x 32n (MT=1, NT=4).
// ---------------------------------------------------------------------------
__global__ void __launch_bounds__(256, 3) gemm_sm(
    const bf16* __restrict__ A, const bf16* __restrict__ B,
    bf16* __restrict__ C, int M, int N, int K,
    size_t Aplane, size_t Bplane, size_t Cplane, Scat rs, Scat cs)
{
    constexpr int BM = 64, BN = 64, BK = 32;
    constexpr int APITCH = BM + 8;      // 72
    constexpr int BPITCH = BN + 8;      // 72
    constexpr int AS_PLANE = BK * APITCH;
    constexpr int BS_PLANE = BK * BPITCH;
    constexpr int STAGE = 2 * AS_PLANE + 2 * BS_PLANE;
    constexpr int NSTG = 3;
    constexpr int NT = 4;               // n8 tiles per warp (32 cols)
    (void)N;

    extern __shared__ bf16 sm[];

    const int tid  = threadIdx.x;
    const int lane = tid & 31;
    const int warp = tid >> 5;
    const int wm = (warp & 3) * 16;
    const int wn = (warp >> 2) * 32;
    const int m0 = blockIdx.x * BM;
    const int n0 = 0;   // grid.y == 1 for all users (N == 64)

    float acc[NT][4];
#pragma unroll
    for (int nt = 0; nt < NT; nt++)
#pragma unroll
        for (int i = 0; i < 4; i++) acc[nt][i] = 0.f;

    const int lk  = tid >> 3;          // 0..31
    const int seg = (tid & 7) * 8;     // 8 elems = 16B

    auto load_stage = [&](int s, int k0) {
        bf16* base = sm + s * STAGE;
        const bf16* Ag = A + (size_t)(k0 + lk) * (size_t)M + (size_t)(m0 + seg);
        cpa16(s2u(base + lk * APITCH + seg), Ag);
        cpa16(s2u(base + AS_PLANE + lk * APITCH + seg), Ag + Aplane);
        bf16* bb = base + 2 * AS_PLANE;
        const bf16* Bg = B + (size_t)(k0 + lk) * 64 + seg;
        cpa16(s2u(bb + lk * BPITCH + seg), Bg);
        cpa16(s2u(bb + BS_PLANE + lk * BPITCH + seg), Bg + Bplane);
    };

    const int nchunks = K / BK;
    load_stage(0, 0);
    CP_COMMIT();
    if (nchunks > 1) load_stage(1, BK);
    CP_COMMIT();

    for (int c = 0; c < nchunks; c++) {
        CP_WAIT1();
        __syncthreads();

        if (c + 2 < nchunks) load_stage((c + 2) % NSTG, (c + 2) * BK);
        CP_COMMIT();

        const bf16* base = sm + (c % NSTG) * STAGE;
        const bf16* Ah = base;
        const bf16* Al = base + AS_PLANE;
        const bf16* Bh = base + 2 * AS_PLANE;
        const bf16* Bl = base + 2 * AS_PLANE + BS_PLANE;

#pragma unroll
        for (int kk = 0; kk < BK; kk += 16) {
            uint32_t a0[4], a1[4];
            const int akr = kk + (lane & 7) + ((lane >> 4) & 1) * 8;
            const int amc = wm + ((lane >> 3) & 1) * 8;
            ldsm4t(a0, s2u(Ah + akr * APITCH + amc));
            ldsm4t(a1, s2u(Al + akr * APITCH + amc));

            uint32_t bf[NT / 2][4];
            const int bkr = kk + (lane & 7) + ((lane >> 3) & 1) * 8;
            const int bnc = wn + ((lane >> 4) & 1) * 8;
#pragma unroll
            for (int np = 0; np < NT / 2; np++)
                ldsm4t(bf[np], s2u(Bh + bkr * BPITCH + bnc + np * 16));
#pragma unroll
            for (int nt = 0; nt < NT; nt++)
                mma16816(acc[nt], a0, &bf[nt >> 1][(nt & 1) * 2]);
#pragma unroll
            for (int nt = 0; nt < NT; nt++)
                mma16816(acc[nt], a1, &bf[nt >> 1][(nt & 1) * 2]);
#pragma unroll
            for (int np = 0; np < NT / 2; np++)
                ldsm4t(bf[np], s2u(Bl + bkr * BPITCH + bnc + np * 16));
#pragma unroll
            for (int nt = 0; nt < NT; nt++)
                mma16816(acc[nt], a0, &bf[nt >> 1][(nt & 1) * 2]);
        }
    }

    const int r  = lane >> 2;
    const int c2 = (lane & 3) * 2;
    int fo[2], go[NT];
    fo[0] = scat_off(m0 + wm + r,     rs);
    fo[1] = scat_off(m0 + wm + r + 8, rs);
#pragma unroll
    for (int nt = 0; nt < NT; nt++)
        go[nt] = scat_off(n0 + wn + nt * 8 + c2, cs);

#pragma unroll
    for (int nt = 0; nt < NT; nt++)
#pragma unroll
        for (int h = 0; h < 2; h++)
            store_pair(C, Cplane, (size_t)(fo[h] + go[nt]),
                       acc[nt][h * 2], acc[nt][h * 2 + 1]);
}

// ---------------------------------------------------------------------------
// Fused prep kernel (round-6): split inputs into bf16 hi/lo pairs.
// ---------------------------------------------------------------------------
__device__ __forceinline__ void put_split_g(bf16* dst, size_t plane, size_t i, float x) {
    bf16 h = __float2bfloat16(x);
    dst[i] = h;
    dst[plane + i] = __float2bfloat16(x - __bfloat162float(h));
}

__global__ void prep_all(const float* __restrict__ state,
                         const float* __restrict__ layer,
                         const float* __restrict__ oper) {
    int idx = blockIdx.x * blockDim.x + threadIdx.x;   // 1,605,632 total
    if (idx < 524288) {
        put_split_g(g_S, 524288, idx, state[idx]);
    } else if (idx < 1048576) {
        int i = idx - 524288;
        put_split_g(g_U, 524288, i, layer[i]);
    } else if (idx < 1081344) {
        int i = idx - 1048576;
        put_split_g(g_O, 32768, i, oper[i]);
    } else {
        int i = idx - 1081344;
        int Lb = i & 15; int t = i >> 4;
        int j  = t & 15;   t >>= 4;
        int ii = t & 15;   t >>= 4;
        int l  = t & 15;   t >>= 4;
        int q  = t;
        float x = layer[((((size_t)q * 16 + l) * 16 + j) * 16 + ii) * 16 + Lb];
        put_split_g(g_Ud, 524288, i, x);
    }
}

// ---------------------------------------------------------------------------
// Fused site-0 boundary (round-6, exact fp32)
// ---------------------------------------------------------------------------
__global__ void s0_all(const float* __restrict__ st, const float* __restrict__ ly,
                       const float* __restrict__ op, bf16* __restrict__ env) {
    extern __shared__ float sf[];
    float* sY  = sf;           // [k*1024 + M*64 + B]
    float* sC2 = sf + 16384;   // [L*64 + k*4 + O]
    float* sC1 = sf + 17408;   // [j*16 + L]
    const int t = threadIdx.x;
    const int A = blockIdx.x;

    {
        int j = t >> 4, L = t & 15;
        float s = 0.f;
        for (int i = 0; i < 16; i++)
            s += st[i * 64 + A] * ly[j * 256 + i * 16 + L];
        sC1[t] = s;
    }
    for (int e = t; e < 16384; e += 256) {
        int k = e >> 10, M = (e >> 6) & 15, B = e & 63;
        float s = 0.f;
        for (int sx = 0; sx < 16; sx++)
            s += ly[k * 256 + sx * 16 + M] * st[sx * 64 + B];
        sY[e] = s;
    }
    __syncthreads();
    for (int e = t; e < 1024; e += 256) {
        int L = e >> 6, k = (e >> 2) & 15, O = e & 3;
        float s = 0.f;
        for (int j = 0; j < 16; j++)
            s += sC1[j * 16 + L] * op[j * 64 + k * 4 + O];
        sC2[e] = s;
    }
    __syncthreads();
    for (int e = t; e < 65536; e += 256) {
        int B = e & 63, M = (e >> 6) & 15, O = (e >> 10) & 3, L = e >> 12;
        float v = 0.f;
#pragma unroll
        for (int k = 0; k < 16; k++)
            v += sC2[L * 64 + k * 4 + O] * sY[k * 1024 + M * 64 + B];
        size_t off = (size_t)A * 65536 + e;
        bf16 h = __float2bfloat16(v);
        env[off] = h;
        env[ESZ + off] = __float2bfloat16(v - __bfloat162float(h));
    }
}

// ---------------------------------------------------------------------------
// Site-7 boundary (round-6)
// ---------------------------------------------------------------------------
__global__ void s7_x1(const float* __restrict__ st, const float* __restrict__ ly,
                      float* __restrict__ X1) {
    int idx = blockIdx.x * blockDim.x + threadIdx.x;
    if (idx >= 16384) return;
    int j = idx & 15, l = (idx >> 4) & 15, a = idx >> 8;
    float s = 0.f;
    for (int i = 0; i < 16; i++)
        s += st[a * 1024 + i * 64] * ly[l * 4096 + j * 256 + i * 16];
    X1[idx] = s;
}
__global__ void s7_x2(const float* __restrict__ X1, const float* __restrict__ op,
                      float* __restrict__ X2) {
    int idx = blockIdx.x * blockDim.x + threadIdx.x;
    if (idx >= 65536) return;
    int k = idx & 15, o = (idx >> 4) & 3, l = (idx >> 6) & 15, a = idx >> 10;
    float s = 0.f;
    for (int j = 0; j < 16; j++)
        s += X1[(a * 16 + l) * 16 + j] * op[o * 1024 + j * 64 + k * 4];
    X2[idx] = s;
}
__global__ void s7_x3(const float* __restrict__ X2, const float* __restrict__ ly,
                      float* __restrict__ X3) {
    int idx = blockIdx.x * blockDim.x + threadIdx.x;
    if (idx >= 1048576) return;
    int s5 = idx & 15, m = (idx >> 4) & 15, o = (idx >> 8) & 3,
        l = (idx >> 10) & 15, a = idx >> 14;
    float s = 0.f;
    for (int k = 0; k < 16; k++)
        s += X2[((a * 16 + l) * 4 + o) * 16 + k] * ly[m * 4096 + k * 256 + s5 * 16];
    X3[idx] = s;
}
__global__ void s7_dot(const float* __restrict__ X3, const float* __restrict__ st,
                       const bf16* __restrict__ env, float* __restrict__ partial) {
    __shared__ float red[256];
    int t = blockIdx.x * 256 + threadIdx.x;
    float x3[16];
#pragma unroll
    for (int s = 0; s < 16; s++) x3[s] = X3[t * 16 + s];
    size_t base = (size_t)t * 64;
    float acc = 0.f;
    for (int b = 0; b < 64; b++) {
        float w = 0.f;
#pragma unroll
        for (int s = 0; s < 16; s++) w += x3[s] * st[b * 1024 + s * 64];
        float e = __bfloat162float(env[base + b]) + __bfloat162float(env[ESZ + base + b]);
        acc += e * w;
    }
    red[threadIdx.x] = acc;
    __syncthreads();
    for (int step = 128; step > 0; step >>= 1) {
        if (threadIdx.x < step) red[threadIdx.x] += red[threadIdx.x + step];
        __syncthreads();
    }
    if (threadIdx.x == 0) partial[blockIdx.x] = red[0];
}
__global__ void s7_reduce(const float* __restrict__ partial, float* __restrict__ out) {
    __shared__ float red[256];
    red[threadIdx.x] = partial[threadIdx.x];
    __syncthreads();
    for (int step = 128; step > 0; step >>= 1) {
        if (threadIdx.x < step) red[threadIdx.x] += red[threadIdx.x + step];
        __syncthreads();
    }
    if (threadIdx.x == 0) out[0] = red[0];
}

// ---------------------------------------------------------------------------
extern "C" void kernel_launch(void* const* d_in, const int* in_sizes, int n_in,
                              void* d_out, int out_size) {
    const float* state = (const float*)d_in[0];  // [8, 64, 16, 64]
    const float* layer = (const float*)d_in[1];  // [1, 8, 16, 16, 16, 16]
    const float* oper  = (const float*)d_in[2];  // [8, 4, 16, 16, 4]
    float* out = (float*)d_out;

    bf16 *TA, *TB, *envA, *envB, *S, *U, *Ud, *O;
    cudaGetSymbolAddress((void**)&TA,   g_TA);
    cudaGetSymbolAddress((void**)&TB,   g_TB);
    cudaGetSymbolAddress((void**)&envA, g_envA);
    cudaGetSymbolAddress((void**)&envB, g_envB);
    cudaGetSymbolAddress((void**)&S,    g_S);
    cudaGetSymbolAddress((void**)&U,    g_U);
    cudaGetSymbolAddress((void**)&Ud,   g_Ud);
    cudaGetSymbolAddress((void**)&O,    g_O);

    // fp32 scratch carved from TB (used only after main loop frees it)
    float* fB = (float*)TB;
    float* X1 = fB, *X2 = fB + 32768, *X3 = fB + 131072;
    float* partial = fB + 1310720;

    constexpr int SMEM128 = 3 * (2 * (32 * 136) + 2 * (32 * 136)) * 2;  // 104448
    constexpr int SMEM64  = 3 * (2 * (32 * 72) + 2 * (32 * 72)) * 2;    // 55296
    constexpr int SMEM_S0 = 17664 * 4;                                  // 70656
    cudaFuncSetAttribute(gemm_big, cudaFuncAttributeMaxDynamicSharedMemorySize, SMEM128);
    cudaFuncSetAttribute(gemm_sm,  cudaFuncAttributeMaxDynamicSharedMemorySize, SMEM64);
    cudaFuncSetAttribute(s0_all,   cudaFuncAttributeMaxDynamicSharedMemorySize, SMEM_S0);

    prep_all<<<6272, 256>>>(state, layer, oper);
    s0_all<<<64, 256, SMEM_S0>>>(state, layer, oper, envA);

    bf16* envc = envA;
    bf16* envn = envB;

    for (int q = 1; q <= 6; q++) {
        const bf16* Sq  = S  + (size_t)q * 65536;
        const bf16* Uq  = U  + (size_t)q * 65536;
        const bf16* Udq = Ud + (size_t)q * 65536;
        const bf16* Oq  = O  + (size_t)q * 4096;

        // G1: T1 = env x S      M=65536 N=1024 K=64   (env -> TA)
        {
            Scat rs = {{64, 16, 4, 16}, {64, 4096, 65536, 4194304}};
            Scat cs = {{64, 16, 1, 1}, {1, 262144, 0, 0}};
            gemm_big<<<dim3(65536 / 128, 1024 / 128), 256, SMEM128>>>(
                envc, Sq, TA, 65536, 1024, 64, ESZ, 524288, TSZ, rs, cs);
        }
        // G2: T2 = T1 x Ud      M=262144 N=256 K=256  (TA -> TB)
        {
            Scat rs = {{64, 64, 16, 4}, {16, 1024, 65536, 16777216}};
            Scat cs = {{16, 16, 1, 1}, {1, 1048576, 0, 0}};
            gemm_big<<<dim3(262144 / 128, 256 / 128), 256, SMEM128>>>(
                TA, Udq, TB, 262144, 256, 256, TSZ, 524288, TSZ, rs, cs);
        }
        // G3: T3 = T2 x O       M=1048576 N=64 K=64   (TB -> TA), small tiles
        {
            Scat rs = {{16, 64, 64, 16}, {4, 64, 4096, 4194304}};
            Scat cs = {{4, 16, 1, 1}, {1, 262144, 0, 0}};
            gemm_sm<<<dim3(1048576 / 64, 1), 256, SMEM64>>>(
                TB, Oq, TA, 1048576, 64, 64, TSZ, 32768, TSZ, rs, cs);
        }
        // G4: T4 = T3 x U       M=262144 N=256 K=256  (TA -> TB)
        {
            Scat rs = {{4, 16, 64, 64}, {16, 64, 1024, 1048576}};
            Scat cs = {{16, 16, 1, 1}, {1, 65536, 0, 0}};
            gemm_big<<<dim3(262144 / 128, 256 / 128), 256, SMEM128>>>(
                TA, Uq, TB, 262144, 256, 256, TSZ, 524288, TSZ, rs, cs);
        }
        // G5: env' = T4 x S     M=65536 N=64 K=1024   (TB -> env), small tiles
        {
            Scat rs = {{16, 4, 16, 64}, {64, 1024, 4096, 65536}};
            Scat cs = {{64, 1, 1, 1}, {1, 0, 0, 0}};
            gemm_sm<<<dim3(65536 / 64, 1), 256, SMEM64>>>(
                TB, Sq, envn, 65536, 64, 1024, TSZ, 524288, ESZ, rs, cs);
        }

        bf16* t = envc; envc = envn; envn = t;
    }

    // Site 7 boundary
    const float* st7 = state + 7 * 65536;
    const float* ly7 = layer + 7 * 65536;
    const float* op7 = oper  + 7 * 4096;
    s7_x1<<<64, 256>>>(st7, ly7, X1);
    s7_x2<<<256, 256>>>(X1, op7, X2);
    s7_x3<<<4096, 256>>>(X2, ly7, X3);
    s7_dot<<<256, 256>>>(X3, st7, envc, partial);
    s7_reduce<<<1, 256>>>(partial, out);
}

// round 10
// speedup vs baseline: 4.3742x; 1.0041x over previous
#include <cuda_runtime.h>
#include <cuda_bf16.h>
#include <cstdint>

using bf16 = __nv_bfloat16;

#define NQ 8
#define TSZ 67108864UL   // elements per T plane
#define ESZ 4194304UL    // elements per env plane

// Static device scratch. hi plane [0,P), lo plane [P,2P).
__device__ bf16 g_TA[2 * TSZ];
__device__ bf16 g_TB[2 * TSZ];
__device__ bf16 g_envA[2 * ESZ];
__device__ bf16 g_envB[2 * ESZ];
__device__ bf16 g_S[2 * 524288];   // state split  (native layout)
__device__ bf16 g_U[2 * 524288];   // layer split  (native layout)
__device__ bf16 g_Ud[2 * 524288];  // permuted U-dagger split
__device__ bf16 g_O[2 * 32768];    // operator split (native layout)

struct Scat { int radix[4]; int stride[4]; };

__device__ __forceinline__ int scat_off(int idx, const Scat s) {
    int off = 0;
#pragma unroll
    for (int d = 0; d < 4; d++) {
        off += (idx % s.radix[d]) * s.stride[d];
        idx /= s.radix[d];
    }
    return off;
}

// ---------------------------------------------------------------------------
// PTX helpers
// ---------------------------------------------------------------------------
__device__ __forceinline__ uint32_t s2u(const void* p) {
    return (uint32_t)__cvta_generic_to_shared(p);
}
__device__ __forceinline__ void cpa16(uint32_t saddr, const void* g) {
    asm volatile("cp.async.cg.shared.global [%0], [%1], 16;\n" :: "r"(saddr), "l"(g));
}
#define CP_COMMIT() asm volatile("cp.async.commit_group;\n")
#define CP_WAIT1()  asm volatile("cp.async.wait_group 1;\n")

__device__ __forceinline__ void ldsm4t(uint32_t* r, uint32_t addr) {
    asm volatile("ldmatrix.sync.aligned.m8n8.x4.trans.shared.b16 {%0,%1,%2,%3}, [%4];"
                 : "=r"(r[0]), "=r"(r[1]), "=r"(r[2]), "=r"(r[3]) : "r"(addr));
}
__device__ __forceinline__ void mma16816(float* d, const uint32_t* a, const uint32_t* b) {
    asm volatile(
        "mma.sync.aligned.m16n8k16.row.col.f32.bf16.bf16.f32 "
        "{%0,%1,%2,%3},{%4,%5,%6,%7},{%8,%9},{%0,%1,%2,%3};"
        : "+f"(d[0]), "+f"(d[1]), "+f"(d[2]), "+f"(d[3])
        : "r"(a[0]), "r"(a[1]), "r"(a[2]), "r"(a[3]), "r"(b[0]), "r"(b[1]));
}

__device__ __forceinline__ void store_pair(bf16* C, size_t Cplane, size_t off,
                                           float v0, float v1) {
    __nv_bfloat162 ph, pl;
    ph.x = __float2bfloat16(v0);
    ph.y = __float2bfloat16(v1);
    pl.x = __float2bfloat16(v0 - __bfloat162float(ph.x));
    pl.y = __float2bfloat16(v1 - __bfloat162float(ph.y));
    *(__nv_bfloat162*)(C + off) = ph;
    *(__nv_bfloat162*)(C + Cplane + off) = pl;
}

// ---------------------------------------------------------------------------
// Split-precision bf16 3-pass GEMM, BM=128, BN=128.
//   acc = Ahi*Bhi + Ahi*Blo + Alo*Bhi (fp32 accum).
// B-hi and B-lo live in separate registers; A-lo is reloaded over A-hi's regs
// AFTER pass 3 is issued, so its LDS latency hides under pass-3 tensor work.
// ---------------------------------------------------------------------------
__global__ void __launch_bounds__(256, 2) gemm_big(
    const bf16* __restrict__ A, const bf16* __restrict__ B,
    bf16* __restrict__ C, int M, int N, int K,
    size_t Aplane, size_t Bplane, size_t Cplane, Scat rs, Scat cs)
{
    constexpr int BM = 128, BN = 128, BK = 32;
    constexpr int APITCH = BM + 8;
    constexpr int BPITCH = BN + 8;
    constexpr int AS_PLANE = BK * APITCH;
    constexpr int BS_PLANE = BK * BPITCH;
    constexpr int STAGE = 2 * AS_PLANE + 2 * BS_PLANE;
    constexpr int NSTG = 3;
    constexpr int NT = BN / 16;   // 8
    constexpr int MT = 2;

    extern __shared__ bf16 sm[];

    const int tid  = threadIdx.x;
    const int lane = tid & 31;
    const int warp = tid >> 5;
    const int wm = (warp & 3) * 32;
    const int wn = (warp >> 2) * (BN / 2);
    const int m0 = blockIdx.x * BM;
    const int n0 = blockIdx.y * BN;

    float acc[MT][NT][4];
#pragma unroll
    for (int mt = 0; mt < MT; mt++)
#pragma unroll
        for (int nt = 0; nt < NT; nt++)
#pragma unroll
            for (int i = 0; i < 4; i++) acc[mt][nt][i] = 0.f;

    const int lk   = tid >> 3;
    const int mseg = (tid & 7) * 16;

    auto load_stage = [&](int s, int k0) {
        bf16* base = sm + s * STAGE;
        const bf16* Ag = A + (size_t)(k0 + lk) * (size_t)M + (size_t)(m0 + mseg);
        uint32_t da = s2u(base + lk * APITCH + mseg);
        cpa16(da,      Ag);
        cpa16(da + 16, Ag + 8);
        uint32_t dal = s2u(base + AS_PLANE + lk * APITCH + mseg);
        cpa16(dal,      Ag + Aplane);
        cpa16(dal + 16, Ag + Aplane + 8);
        bf16* bb = base + 2 * AS_PLANE;
        const bf16* Bg = B + (size_t)(k0 + lk) * (size_t)N + (size_t)(n0 + mseg);
        uint32_t db = s2u(bb + lk * BPITCH + mseg);
        cpa16(db,      Bg);
        cpa16(db + 16, Bg + 8);
        uint32_t dbl = s2u(bb + BS_PLANE + lk * BPITCH + mseg);
        cpa16(dbl,      Bg + Bplane);
        cpa16(dbl + 16, Bg + Bplane + 8);
    };

    const int nchunks = K / BK;
    load_stage(0, 0);
    CP_COMMIT();
    if (nchunks > 1) load_stage(1, BK);
    CP_COMMIT();

    for (int c = 0; c < nchunks; c++) {
        CP_WAIT1();
        __syncthreads();

        if (c + 2 < nchunks) load_stage((c + 2) % NSTG, (c + 2) * BK);
        CP_COMMIT();

        const bf16* base = sm + (c % NSTG) * STAGE;
        const bf16* Ah = base;
        const bf16* Al = base + AS_PLANE;
        const bf16* Bh = base + 2 * AS_PLANE;
        const bf16* Bl = base + 2 * AS_PLANE + BS_PLANE;

#pragma unroll
        for (int kk = 0; kk < BK; kk += 16) {
            uint32_t a[MT][4];
            uint32_t bh[NT / 2][4], bl[NT / 2][4];
            const int akr = kk + (lane & 7) + ((lane >> 4) & 1) * 8;
            const int amc = wm + ((lane >> 3) & 1) * 8;
            const int bkr = kk + (lane & 7) + ((lane >> 3) & 1) * 8;
            const int bnc = wn + ((lane >> 4) & 1) * 8;
#pragma unroll
            for (int mt = 0; mt < MT; mt++)
                ldsm4t(a[mt], s2u(Ah + akr * APITCH + amc + mt * 16));
#pragma unroll
            for (int np = 0; np < NT / 2; np++) {
                ldsm4t(bh[np], s2u(Bh + bkr * BPITCH + bnc + np * 16));
                ldsm4t(bl[np], s2u(Bl + bkr * BPITCH + bnc + np * 16));
            }
            // pass 1: Ahi * Bhi
#pragma unroll
            for (int mt = 0; mt < MT; mt++)
#pragma unroll
                for (int nt = 0; nt < NT; nt++)
                    mma16816(acc[mt][nt], a[mt], &bh[nt >> 1][(nt & 1) * 2]);
            // pass 3: Ahi * Blo
#pragma unroll
            for (int mt = 0; mt < MT; mt++)
#pragma unroll
                for (int nt = 0; nt < NT; nt++)
                    mma16816(acc[mt][nt], a[mt], &bl[nt >> 1][(nt & 1) * 2]);
            // reload A-lo (2 ldsm; latency hidden under pass-3 tensor work)
#pragma unroll
            for (int mt = 0; mt < MT; mt++)
                ldsm4t(a[mt], s2u(Al + akr * APITCH + amc + mt * 16));
            // pass 2: Alo * Bhi
#pragma unroll
            for (int mt = 0; mt < MT; mt++)
#pragma unroll
                for (int nt = 0; nt < NT; nt++)
                    mma16816(acc[mt][nt], a[mt], &bh[nt >> 1][(nt & 1) * 2]);
        }
    }

    const int r  = lane >> 2;
    const int c2 = (lane & 3) * 2;
    int fo[MT][2], go[NT];
#pragma unroll
    for (int mt = 0; mt < MT; mt++) {
        fo[mt][0] = scat_off(m0 + wm + mt * 16 + r,     rs);
        fo[mt][1] = scat_off(m0 + wm + mt * 16 + r + 8, rs);
    }
#pragma unroll
    for (int nt = 0; nt < NT; nt++)
        go[nt] = scat_off(n0 + wn + nt * 8 + c2, cs);

#pragma unroll
    for (int mt = 0; mt < MT; mt++)
#pragma unroll
        for (int nt = 0; nt < NT; nt++)
#pragma unroll
            for (int h = 0; h < 2; h++)
                store_pair(C, Cplane, (size_t)(fo[mt][h] + go[nt]),
                           acc[mt][nt][h * 2], acc[mt][nt][h * 2 + 1]);
}

// ---------------------------------------------------------------------------
// High-occupancy small-tile variant: BM=64, BN=64, 3 CTAs/SM. Same reorder.
// ---------------------------------------------------------------------------
__global__ void __launch_bounds__(256, 3) gemm_sm(
    const bf16* __restrict__ A, const bf16* __restrict__ B,
    bf16* __restrict__ C, int M, int N, int K,
    size_t Aplane, size_t Bplane, size_t Cplane, Scat rs, Scat cs)
{
    constexpr int BM = 64, BN = 64, BK = 32;
    constexpr int APITCH = BM + 8;      // 72
    constexpr int BPITCH = BN + 8;      // 72
    constexpr int AS_PLANE = BK * APITCH;
    constexpr int BS_PLANE = BK * BPITCH;
    constexpr int STAGE = 2 * AS_PLANE + 2 * BS_PLANE;
    constexpr int NSTG = 3;
    constexpr int NT = 4;               // n8 tiles per warp (32 cols)
    (void)N;

    extern __shared__ bf16 sm[];

    const int tid  = threadIdx.x;
    const int lane = tid & 31;
    const int warp = tid >> 5;
    const int wm = (warp & 3) * 16;
    const int wn = (warp >> 2) * 32;
    const int m0 = blockIdx.x * BM;
    const int n0 = 0;   // grid.y == 1 for all users (N == 64)

    float acc[NT][4];
#pragma unroll
    for (int nt = 0; nt < NT; nt++)
#pragma unroll
        for (int i = 0; i < 4; i++) acc[nt][i] = 0.f;

    const int lk  = tid >> 3;          // 0..31
    const int seg = (tid & 7) * 8;     // 8 elems = 16B

    auto load_stage = [&](int s, int k0) {
        bf16* base = sm + s * STAGE;
        const bf16* Ag = A + (size_t)(k0 + lk) * (size_t)M + (size_t)(m0 + seg);
        cpa16(s2u(base + lk * APITCH + seg), Ag);
        cpa16(s2u(base + AS_PLANE + lk * APITCH + seg), Ag + Aplane);
        bf16* bb = base + 2 * AS_PLANE;
        const bf16* Bg = B + (size_t)(k0 + lk) * 64 + seg;
        cpa16(s2u(bb + lk * BPITCH + seg), Bg);
        cpa16(s2u(bb + BS_PLANE + lk * BPITCH + seg), Bg + Bplane);
    };

    const int nchunks = K / BK;
    load_stage(0, 0);
    CP_COMMIT();
    if (nchunks > 1) load_stage(1, BK);
    CP_COMMIT();

    for (int c = 0; c < nchunks; c++) {
        CP_WAIT1();
        __syncthreads();

        if (c + 2 < nchunks) load_stage((c + 2) % NSTG, (c + 2) * BK);
        CP_COMMIT();

        const bf16* base = sm + (c % NSTG) * STAGE;
        const bf16* Ah = base;
        const bf16* Al = base + AS_PLANE;
        const bf16* Bh = base + 2 * AS_PLANE;
        const bf16* Bl = base + 2 * AS_PLANE + BS_PLANE;

#pragma unroll
        for (int kk = 0; kk < BK; kk += 16) {
            uint32_t a[4];
            uint32_t bh[NT / 2][4], bl[NT / 2][4];
            const int akr = kk + (lane & 7) + ((lane >> 4) & 1) * 8;
            const int amc = wm + ((lane >> 3) & 1) * 8;
            const int bkr = kk + (lane & 7) + ((lane >> 3) & 1) * 8;
            const int bnc = wn + ((lane >> 4) & 1) * 8;
            ldsm4t(a, s2u(Ah + akr * APITCH + amc));
#pragma unroll
            for (int np = 0; np < NT / 2; np++) {
                ldsm4t(bh[np], s2u(Bh + bkr * BPITCH + bnc + np * 16));
                ldsm4t(bl[np], s2u(Bl + bkr * BPITCH + bnc + np * 16));
            }
            // pass 1: Ahi * Bhi
#pragma unroll
            for (int nt = 0; nt < NT; nt++)
                mma16816(acc[nt], a, &bh[nt >> 1][(nt & 1) * 2]);
            // pass 3: Ahi * Blo
#pragma unroll
            for (int nt = 0; nt < NT; nt++)
                mma16816(acc[nt], a, &bl[nt >> 1][(nt & 1) * 2]);
            // reload A-lo
            ldsm4t(a, s2u(Al + akr * APITCH + amc));
            // pass 2: Alo * Bhi
#pragma unroll
            for (int nt = 0; nt < NT; nt++)
                mma16816(acc[nt], a, &bh[nt >> 1][(nt & 1) * 2]);
        }
    }

    const int r  = lane >> 2;
    const int c2 = (lane & 3) * 2;
    int fo[2], go[NT];
    fo[0] = scat_off(m0 + wm + r,     rs);
    fo[1] = scat_off(m0 + wm + r + 8, rs);
#pragma unroll
    for (int nt = 0; nt < NT; nt++)
        go[nt] = scat_off(n0 + wn + nt * 8 + c2, cs);

#pragma unroll
    for (int nt = 0; nt < NT; nt++)
#pragma unroll
        for (int h = 0; h < 2; h++)
            store_pair(C, Cplane, (size_t)(fo[h] + go[nt]),
                       acc[nt][h * 2], acc[nt][h * 2 + 1]);
}

// ---------------------------------------------------------------------------
// Fused prep kernel: split inputs into bf16 hi/lo pairs.
// ---------------------------------------------------------------------------
__device__ __forceinline__ void put_split_g(bf16* dst, size_t plane, size_t i, float x) {
    bf16 h = __float2bfloat16(x);
    dst[i] = h;
    dst[plane + i] = __float2bfloat16(x - __bfloat162float(h));
}

__global__ void prep_all(const float* __restrict__ state,
                         const float* __restrict__ layer,
                         const float* __restrict__ oper) {
    int idx = blockIdx.x * blockDim.x + threadIdx.x;   // 1,605,632 total
    if (idx < 524288) {
        put_split_g(g_S, 524288, idx, state[idx]);
    } else if (idx < 1048576) {
        int i = idx - 524288;
        put_split_g(g_U, 524288, i, layer[i]);
    } else if (idx < 1081344) {
        int i = idx - 1048576;
        put_split_g(g_O, 32768, i, oper[i]);
    } else {
        int i = idx - 1081344;
        int Lb = i & 15; int t = i >> 4;
        int j  = t & 15;   t >>= 4;
        int ii = t & 15;   t >>= 4;
        int l  = t & 15;   t >>= 4;
        int q  = t;
        float x = layer[((((size_t)q * 16 + l) * 16 + j) * 16 + ii) * 16 + Lb];
        put_split_g(g_Ud, 524288, i, x);
    }
}

// ---------------------------------------------------------------------------
// Fused site-0 boundary (exact fp32)
// ---------------------------------------------------------------------------
__global__ void s0_all(const float* __restrict__ st, const float* __restrict__ ly,
                       const float* __restrict__ op, bf16* __restrict__ env) {
    extern __shared__ float sf[];
    float* sY  = sf;           // [k*1024 + M*64 + B]
    float* sC2 = sf + 16384;   // [L*64 + k*4 + O]
    float* sC1 = sf + 17408;   // [j*16 + L]
    const int t = threadIdx.x;
    const int A = blockIdx.x;

    {
        int j = t >> 4, L = t & 15;
        float s = 0.f;
        for (int i = 0; i < 16; i++)
            s += st[i * 64 + A] * ly[j * 256 + i * 16 + L];
        sC1[t] = s;
    }
    for (int e = t; e < 16384; e += 256) {
        int k = e >> 10, M = (e >> 6) & 15, B = e & 63;
        float s = 0.f;
        for (int sx = 0; sx < 16; sx++)
            s += ly[k * 256 + sx * 16 + M] * st[sx * 64 + B];
        sY[e] = s;
    }
    __syncthreads();
    for (int e = t; e < 1024; e += 256) {
        int L = e >> 6, k = (e >> 2) & 15, O = e & 3;
        float s = 0.f;
        for (int j = 0; j < 16; j++)
            s += sC1[j * 16 + L] * op[j * 64 + k * 4 + O];
        sC2[e] = s;
    }
    __syncthreads();
    for (int e = t; e < 65536; e += 256) {
        int B = e & 63, M = (e >> 6) & 15, O = (e >> 10) & 3, L = e >> 12;
        float v = 0.f;
#pragma unroll
        for (int k = 0; k < 16; k++)
            v += sC2[L * 64 + k * 4 + O] * sY[k * 1024 + M * 64 + B];
        size_t off = (size_t)A * 65536 + e;
        bf16 h = __float2bfloat16(v);
        env[off] = h;
        env[ESZ + off] = __float2bfloat16(v - __bfloat162float(h));
    }
}

// ---------------------------------------------------------------------------
// Site-7 boundary
// ---------------------------------------------------------------------------
__global__ void s7_x1(const float* __restrict__ st, const float* __restrict__ ly,
                      float* __restrict__ X1) {
    int idx = blockIdx.x * blockDim.x + threadIdx.x;
    if (idx >= 16384) return;
    int j = idx & 15, l = (idx >> 4) & 15, a = idx >> 8;
    float s = 0.f;
    for (int i = 0; i < 16; i++)
        s += st[a * 1024 + i * 64] * ly[l * 4096 + j * 256 + i * 16];
    X1[idx] = s;
}
__global__ void s7_x2(const float* __restrict__ X1, const float* __restrict__ op,
                      float* __restrict__ X2) {
    int idx = blockIdx.x * blockDim.x + threadIdx.x;
    if (idx >= 65536) return;
    int k = idx & 15, o = (idx >> 4) & 3, l = (idx >> 6) & 15, a = idx >> 10;
    float s = 0.f;
    for (int j = 0; j < 16; j++)
        s += X1[(a * 16 + l) * 16 + j] * op[o * 1024 + j * 64 + k * 4];
    X2[idx] = s;
}
__global__ void s7_x3(const float* __restrict__ X2, const float* __restrict__ ly,
                      float* __restrict__ X3) {
    int idx = blockIdx.x * blockDim.x + threadIdx.x;
    if (idx >= 1048576) return;
    int s5 = idx & 15, m = (idx >> 4) & 15, o = (idx >> 8) & 3,
        l = (idx >> 10) & 15, a = idx >> 14;
    float s = 0.f;
    for (int k = 0; k < 16; k++)
        s += X2[((a * 16 + l) * 4 + o) * 16 + k] * ly[m * 4096 + k * 256 + s5 * 16];
    X3[idx] = s;
}
__global__ void s7_dot(const float* __restrict__ X3, const float* __restrict__ st,
                       const bf16* __restrict__ env, float* __restrict__ partial) {
    __shared__ float red[256];
    int t = blockIdx.x * 256 + threadIdx.x;
    float x3[16];
#pragma unroll
    for (int s = 0; s < 16; s++) x3[s] = X3[t * 16 + s];
    size_t base = (size_t)t * 64;
    float acc = 0.f;
    for (int b = 0; b < 64; b++) {
        float w = 0.f;
#pragma unroll
        for (int s = 0; s < 16; s++) w += x3[s] * st[b * 1024 + s * 64];
        float e = __bfloat162float(env[base + b]) + __bfloat162float(env[ESZ + base + b]);
        acc += e * w;
    }
    red[threadIdx.x] = acc;
    __syncthreads();
    for (int step = 128; step > 0; step >>= 1) {
        if (threadIdx.x < step) red[threadIdx.x] += red[threadIdx.x + step];
        __syncthreads();
    }
    if (threadIdx.x == 0) partial[blockIdx.x] = red[0];
}
__global__ void s7_reduce(const float* __restrict__ partial, float* __restrict__ out) {
    __shared__ float red[256];
    red[threadIdx.x] = partial[threadIdx.x];
    __syncthreads();
    for (int step = 128; step > 0; step >>= 1) {
        if (threadIdx.x < step) red[threadIdx.x] += red[threadIdx.x + step];
        __syncthreads();
    }
    if (threadIdx.x == 0) out[0] = red[0];
}

// ---------------------------------------------------------------------------
extern "C" void kernel_launch(void* const* d_in, const int* in_sizes, int n_in,
                              void* d_out, int out_size) {
    const float* state = (const float*)d_in[0];  // [8, 64, 16, 64]
    const float* layer = (const float*)d_in[1];  // [1, 8, 16, 16, 16, 16]
    const float* oper  = (const float*)d_in[2];  // [8, 4, 16, 16, 4]
    float* out = (float*)d_out;

    bf16 *TA, *TB, *envA, *envB, *S, *U, *Ud, *O;
    cudaGetSymbolAddress((void**)&TA,   g_TA);
    cudaGetSymbolAddress((void**)&TB,   g_TB);
    cudaGetSymbolAddress((void**)&envA, g_envA);
    cudaGetSymbolAddress((void**)&envB, g_envB);
    cudaGetSymbolAddress((void**)&S,    g_S);
    cudaGetSymbolAddress((void**)&U,    g_U);
    cudaGetSymbolAddress((void**)&Ud,   g_Ud);
    cudaGetSymbolAddress((void**)&O,    g_O);

    // fp32 scratch carved from TB (used only after main loop frees it)
    float* fB = (float*)TB;
    float* X1 = fB, *X2 = fB + 32768, *X3 = fB + 131072;
    float* partial = fB + 1310720;

    constexpr int SMEM128 = 3 * (2 * (32 * 136) + 2 * (32 * 136)) * 2;  // 104448
    constexpr int SMEM64  = 3 * (2 * (32 * 72) + 2 * (32 * 72)) * 2;    // 55296
    constexpr int SMEM_S0 = 17664 * 4;                                  // 70656
    cudaFuncSetAttribute(gemm_big, cudaFuncAttributeMaxDynamicSharedMemorySize, SMEM128);
    cudaFuncSetAttribute(gemm_sm,  cudaFuncAttributeMaxDynamicSharedMemorySize, SMEM64);
    cudaFuncSetAttribute(s0_all,   cudaFuncAttributeMaxDynamicSharedMemorySize, SMEM_S0);

    prep_all<<<6272, 256>>>(state, layer, oper);
    s0_all<<<64, 256, SMEM_S0>>>(state, layer, oper, envA);

    bf16* envc = envA;
    bf16* envn = envB;

    for (int q = 1; q <= 6; q++) {
        const bf16* Sq  = S  + (size_t)q * 65536;
        const bf16* Uq  = U  + (size_t)q * 65536;
        const bf16* Udq = Ud + (size_t)q * 65536;
        const bf16* Oq  = O  + (size_t)q * 4096;

        // G1: T1 = env x S      M=65536 N=1024 K=64   (env -> TA)
        {
            Scat rs = {{64, 16, 4, 16}, {64, 4096, 65536, 4194304}};
            Scat cs = {{64, 16, 1, 1}, {1, 262144, 0, 0}};
            gemm_big<<<dim3(65536 / 128, 1024 / 128), 256, SMEM128>>>(
                envc, Sq, TA, 65536, 1024, 64, ESZ, 524288, TSZ, rs, cs);
        }
        // G2: T2 = T1 x Ud      M=262144 N=256 K=256  (TA -> TB)
        {
            Scat rs = {{64, 64, 16, 4}, {16, 1024, 65536, 16777216}};
            Scat cs = {{16, 16, 1, 1}, {1, 1048576, 0, 0}};
            gemm_big<<<dim3(262144 / 128, 256 / 128), 256, SMEM128>>>(
                TA, Udq, TB, 262144, 256, 256, TSZ, 524288, TSZ, rs, cs);
        }
        // G3: T3 = T2 x O       M=1048576 N=64 K=64   (TB -> TA), small tiles
        {
            Scat rs = {{16, 64, 64, 16}, {4, 64, 4096, 4194304}};
            Scat cs = {{4, 16, 1, 1}, {1, 262144, 0, 0}};
            gemm_sm<<<dim3(1048576 / 64, 1), 256, SMEM64>>>(
                TB, Oq, TA, 1048576, 64, 64, TSZ, 32768, TSZ, rs, cs);
        }
        // G4: T4 = T3 x U       M=262144 N=256 K=256  (TA -> TB)
        {
            Scat rs = {{4, 16, 64, 64}, {16, 64, 1024, 1048576}};
            Scat cs = {{16, 16, 1, 1}, {1, 65536, 0, 0}};
            gemm_big<<<dim3(262144 / 128, 256 / 128), 256, SMEM128>>>(
                TA, Uq, TB, 262144, 256, 256, TSZ, 524288, TSZ, rs, cs);
        }
        // G5: env' = T4 x S     M=65536 N=64 K=1024   (TB -> env), small tiles
        {
            Scat rs = {{16, 4, 16, 64}, {64, 1024, 4096, 65536}};
            Scat cs = {{64, 1, 1, 1}, {1, 0, 0, 0}};
            gemm_sm<<<dim3(65536 / 64, 1), 256, SMEM64>>>(
                TB, Sq, envn, 65536, 64, 1024, TSZ, 524288, ESZ, rs, cs);
        }

        bf16* t = envc; envc = envn; envn = t;
    }

    // Site 7 boundary
    const float* st7 = state + 7 * 65536;
    const float* ly7 = layer + 7 * 65536;
    const float* op7 = oper  + 7 * 4096;
    s7_x1<<<64, 256>>>(st7, ly7, X1);
    s7_x2<<<256, 256>>>(X1, op7, X2);
    s7_x3<<<4096, 256>>>(X2, ly7, X3);
    s7_dot<<<256, 256>>>(X3, st7, envc, partial);
    s7_reduce<<<1, 256>>>(partial, out);
}